// round 4
// baseline (speedup 1.0000x reference)
#include <cuda_runtime.h>
#include <math.h>
#include <stdint.h>

#define N_IMG   4
#define C       256
#define HW      4096
#define THREE_C 768

// Scratch (device globals: allocation-free rule)
__device__ float g_scale[C];
__device__ float g_shift[C];
__device__ float g_seq[N_IMG * HW * C];        // normalized, (n, hw, c)
__device__ float g_qkv[N_IMG * HW * THREE_C];  // (n, hw, 3c)
__device__ float g_o[N_IMG * HW * C];          // attention output, (n, hw, c)

__device__ __forceinline__ uint32_t f2tf32(float x) {
    uint32_t u;
    asm("cvt.rna.tf32.f32 %0, %1;" : "=r"(u) : "f"(x));
    return u;
}

// m16n8k8 tf32 mma (portable sm_80+ ISA)
__device__ __forceinline__ void mma8(float* d, const uint32_t* a,
                                     uint32_t b0, uint32_t b1) {
    asm volatile(
        "mma.sync.aligned.m16n8k8.row.col.f32.tf32.tf32.f32 "
        "{%0,%1,%2,%3}, {%4,%5,%6,%7}, {%8,%9}, {%0,%1,%2,%3};"
        : "+f"(d[0]), "+f"(d[1]), "+f"(d[2]), "+f"(d[3])
        : "r"(a[0]), "r"(a[1]), "r"(a[2]), "r"(a[3]), "r"(b0), "r"(b1));
}

// Shared layout (float indices). No Q tile (Q frags live in registers).
#define KS_OFF 0                      // K: 64 x 64, pitch 68
#define VS_OFF (KS_OFF + 64 * 68)     // V: 64 x 64, pitch 72
#define PS_OFF (VS_OFF + 64 * 72)     // P: 128 x 64, pitch 68
#define SMEM_ATTN_F (PS_OFF + 128 * 68)
#define SMEM_ATTN_B (SMEM_ATTN_F * 4)   // 70656 bytes -> 3 CTAs/SM

// ===========================================================================
// mma.sync tf32 flash attention, no-max-subtraction softmax.
// Grid (32 q-tiles of 128, 16 n*h). 128 threads = 4 warps, 32 q-rows/warp.
// Q A-fragments are loaded once into registers (64 u32/thread).
// Faithful-reshape indexing: head-row r -> seq p = h*1024 + r/4, s = r%4;
// Q col 192s+d, K +64, V +128; output col 64s+d.
// ===========================================================================
__global__ __launch_bounds__(128, 3) void attn_mma() {
    extern __shared__ float smf[];
    uint32_t* smu = (uint32_t*)smf;

    const int t    = threadIdx.x;
    const int w    = t >> 5;
    const int lane = t & 31;
    const int g    = lane >> 2;   // row within fragment group
    const int q4   = lane & 3;    // col phase
    const int rb   = w * 32;      // warp's q-row base within tile

    const int qt = blockIdx.x;
    const int nh = blockIdx.y;
    const int n  = nh >> 2, h = nh & 3;
    const float* qkv = g_qkv + (size_t)n * HW * THREE_C;

    const int d4 = (t & 15) * 4;  // float4 column for K/V loads
    const int rl = t >> 4;        // row lane 0..7

    // ---- Load Q A-fragments into registers (once) ----
    // aq[mt][ks][0]=(g,q4) [1]=(g+8,q4) [2]=(g,q4+4) [3]=(g+8,q4+4)
    uint32_t aq[2][8][4];
#pragma unroll
    for (int mt = 0; mt < 2; mt++) {
#pragma unroll
        for (int rr = 0; rr < 2; rr++) {
            int r  = qt * 128 + rb + mt * 16 + rr * 8 + g;
            int p  = h * 1024 + (r >> 2);
            int s  = r & 3;
            const float* qrow = qkv + (size_t)p * 768 + s * 192;
#pragma unroll
            for (int ks = 0; ks < 8; ks++) {
                aq[mt][ks][rr]     = f2tf32(qrow[ks * 8 + q4]);
                aq[mt][ks][rr + 2] = f2tf32(qrow[ks * 8 + q4 + 4]);
            }
        }
    }

    float co[2][8][4] = {};
    float lsum[2][2]  = {};

    for (int kt = 0; kt < 64; kt++) {
        // ---- Load K, V tiles (64 x 64 each) ----
#pragma unroll
        for (int i = 0; i < 8; i++) {
            int row = 8 * i + rl;
            int rg  = kt * 64 + row;
            int p   = h * 1024 + (rg >> 2);
            int s   = rg & 3;
            const float* base = &qkv[(size_t)p * 768 + s * 192];
            float4 kv = *(const float4*)&base[64 + d4];
            float4 vv = *(const float4*)&base[128 + d4];
            *(uint4*)&smu[KS_OFF + row * 68 + d4] =
                make_uint4(f2tf32(kv.x), f2tf32(kv.y), f2tf32(kv.z), f2tf32(kv.w));
            *(uint4*)&smu[VS_OFF + row * 72 + d4] =
                make_uint4(f2tf32(vv.x), f2tf32(vv.y), f2tf32(vv.z), f2tf32(vv.w));
        }
        __syncthreads();

        // ---- S = Q K^T in two nt-halves (saves sc registers) ----
#pragma unroll
        for (int half = 0; half < 2; half++) {
            float sc[2][4][4] = {};
#pragma unroll
            for (int ks = 0; ks < 8; ks++) {
#pragma unroll
                for (int nt = 0; nt < 4; nt++) {
                    int kr = (half * 4 + nt) * 8 + g;
                    uint32_t b0 = smu[KS_OFF + kr * 68 + ks * 8 + q4];
                    uint32_t b1 = smu[KS_OFF + kr * 68 + ks * 8 + q4 + 4];
                    mma8(sc[0][nt], aq[0][ks], b0, b1);
                    mma8(sc[1][nt], aq[1][ks], b0, b1);
                }
            }
            // softmax (exp of scaled scores), P -> smem as tf32
#pragma unroll
            for (int mt = 0; mt < 2; mt++) {
                int r0 = rb + mt * 16 + g;
#pragma unroll
                for (int nt = 0; nt < 4; nt++) {
                    int colb = (half * 4 + nt) * 8;
                    float p0 = __expf(sc[mt][nt][0] * 0.125f);
                    float p1 = __expf(sc[mt][nt][1] * 0.125f);
                    float p2 = __expf(sc[mt][nt][2] * 0.125f);
                    float p3 = __expf(sc[mt][nt][3] * 0.125f);
                    lsum[mt][0] += p0 + p1;
                    lsum[mt][1] += p2 + p3;
                    *(uint2*)&smu[PS_OFF + r0 * 68 + colb + 2 * q4] =
                        make_uint2(f2tf32(p0), f2tf32(p1));
                    *(uint2*)&smu[PS_OFF + (r0 + 8) * 68 + colb + 2 * q4] =
                        make_uint2(f2tf32(p2), f2tf32(p3));
                }
            }
        }
        __syncwarp();

        // ---- O += P V : per warp 32x64 ----
#pragma unroll
        for (int ks = 0; ks < 8; ks++) {
            uint32_t af[2][4];
#pragma unroll
            for (int mt = 0; mt < 2; mt++) {
                int r0 = rb + mt * 16 + g;
                int cc = ks * 8 + q4;
                af[mt][0] = smu[PS_OFF + r0 * 68 + cc];
                af[mt][1] = smu[PS_OFF + (r0 + 8) * 68 + cc];
                af[mt][2] = smu[PS_OFF + r0 * 68 + cc + 4];
                af[mt][3] = smu[PS_OFF + (r0 + 8) * 68 + cc + 4];
            }
#pragma unroll
            for (int nt = 0; nt < 8; nt++) {
                uint32_t b0 = smu[VS_OFF + (ks * 8 + q4) * 72 + nt * 8 + g];
                uint32_t b1 = smu[VS_OFF + (ks * 8 + q4 + 4) * 72 + nt * 8 + g];
                mma8(co[0][nt], af[0], b0, b1);
                mma8(co[1][nt], af[1], b0, b1);
            }
        }
        __syncthreads();
    }

    // ---- finalize: quad row-sum reduce, normalize, stage, store ----
    float inv[2][2];
#pragma unroll
    for (int mt = 0; mt < 2; mt++)
#pragma unroll
        for (int hh = 0; hh < 2; hh++) {
            float l = lsum[mt][hh];
            l += __shfl_xor_sync(0xffffffffu, l, 1);
            l += __shfl_xor_sync(0xffffffffu, l, 2);
            inv[mt][hh] = 1.f / l;
        }
#pragma unroll
    for (int mt = 0; mt < 2; mt++) {
        int r0 = rb + mt * 16 + g;
#pragma unroll
        for (int nt = 0; nt < 8; nt++) {
            smf[PS_OFF + r0 * 68 + nt * 8 + 2 * q4]           = co[mt][nt][0] * inv[mt][0];
            smf[PS_OFF + r0 * 68 + nt * 8 + 2 * q4 + 1]       = co[mt][nt][1] * inv[mt][0];
            smf[PS_OFF + (r0 + 8) * 68 + nt * 8 + 2 * q4]     = co[mt][nt][2] * inv[mt][1];
            smf[PS_OFF + (r0 + 8) * 68 + nt * 8 + 2 * q4 + 1] = co[mt][nt][3] * inv[mt][1];
        }
    }
    __syncthreads();
    {
        int rg = qt * 128 + t;
        int p  = h * 1024 + (rg >> 2);
        int s  = rg & 3;
        float* dst = g_o + ((size_t)n * HW + p) * C + s * 64;
#pragma unroll
        for (int i = 0; i < 16; i++)
            *(float4*)&dst[4 * i] = *(float4*)&smf[PS_OFF + t * 68 + 4 * i];
    }
}

// ---------------------------------------------------------------------------
// 1) BatchNorm statistics -> per-channel scale/shift
// ---------------------------------------------------------------------------
__global__ void bn_stats(const float* __restrict__ x,
                         const float* __restrict__ gamma,
                         const float* __restrict__ beta) {
    int c = blockIdx.x;
    int t = threadIdx.x;
    float s = 0.f, s2 = 0.f;
    for (int n = 0; n < N_IMG; n++) {
        const float* p = x + ((size_t)n * C + c) * HW;
        for (int i = t; i < HW; i += 256) {
            float v = p[i];
            s += v;
            s2 += v * v;
        }
    }
    __shared__ float sh0[256], sh1[256];
    sh0[t] = s; sh1[t] = s2;
    __syncthreads();
    for (int o = 128; o > 0; o >>= 1) {
        if (t < o) { sh0[t] += sh0[t + o]; sh1[t] += sh1[t + o]; }
        __syncthreads();
    }
    if (t == 0) {
        const float inv = 1.f / (float)(N_IMG * HW);
        float mean = sh0[0] * inv;
        float var  = sh1[0] * inv - mean * mean;
        float rstd = rsqrtf(var + 1e-5f);
        float sc   = gamma[c] * rstd;
        g_scale[c] = sc;
        g_shift[c] = beta[c] - mean * sc;
    }
}

// ---------------------------------------------------------------------------
// 2) Normalize + transpose (n,c,hw) -> (n,hw,c)
// ---------------------------------------------------------------------------
__global__ void norm_transpose(const float* __restrict__ x) {
    __shared__ float tile[32][33];
    int n  = blockIdx.z;
    int c0 = blockIdx.y * 32;
    int p0 = blockIdx.x * 32;
    int tx = threadIdx.x, ty = threadIdx.y;  // 32 x 8
#pragma unroll
    for (int j = 0; j < 4; j++) {
        int c = c0 + ty + j * 8;
        tile[ty + j * 8][tx] =
            x[((size_t)n * C + c) * HW + p0 + tx] * g_scale[c] + g_shift[c];
    }
    __syncthreads();
#pragma unroll
    for (int j = 0; j < 4; j++) {
        int p = p0 + ty + j * 8;
        g_seq[((size_t)n * HW + p) * C + c0 + tx] = tile[tx][ty + j * 8];
    }
}

// ---------------------------------------------------------------------------
// 3) QKV GEMM: (16384 x 256) @ (256 x 768) -> g_qkv
// ---------------------------------------------------------------------------
__global__ __launch_bounds__(256) void gemm_qkv(const float* __restrict__ B) {
    __shared__ float As[32 * 68];
    __shared__ float Bs[32 * 68];
    int m0 = blockIdx.y * 64, n0 = blockIdx.x * 64;
    int t  = threadIdx.x;
    int ty = t >> 4, tx = t & 15;
    float acc[4][4] = {};

    for (int kk = 0; kk < 256; kk += 32) {
#pragma unroll
        for (int l = 0; l < 8; l++) {
            int i = l * 256 + t;
            int m = i >> 5, k = i & 31;
            As[k * 68 + m] = g_seq[(size_t)(m0 + m) * 256 + kk + k];
        }
#pragma unroll
        for (int l = 0; l < 8; l++) {
            int i = l * 256 + t;
            int k = i >> 6, nn = i & 63;
            Bs[k * 68 + nn] = B[(size_t)(kk + k) * 768 + n0 + nn];
        }
        __syncthreads();
#pragma unroll
        for (int k = 0; k < 32; k++) {
            float a[4], b[4];
            *(float4*)a = *(const float4*)&As[k * 68 + 4 * ty];
            *(float4*)b = *(const float4*)&Bs[k * 68 + 4 * tx];
#pragma unroll
            for (int ii = 0; ii < 4; ii++)
#pragma unroll
                for (int jj = 0; jj < 4; jj++)
                    acc[ii][jj] = fmaf(a[ii], b[jj], acc[ii][jj]);
        }
        __syncthreads();
    }
#pragma unroll
    for (int ii = 0; ii < 4; ii++) {
        float4 v = make_float4(acc[ii][0], acc[ii][1], acc[ii][2], acc[ii][3]);
        *(float4*)&g_qkv[(size_t)(m0 + 4 * ty + ii) * 768 + n0 + 4 * tx] = v;
    }
}

// ---------------------------------------------------------------------------
// 5) Proj GEMM: (16384 x 256) @ (256 x 256) + b -> out (n,c,h,w)
// ---------------------------------------------------------------------------
__global__ __launch_bounds__(256) void gemm_proj(const float* __restrict__ B,
                                                 const float* __restrict__ bias,
                                                 float* __restrict__ out) {
    __shared__ float shm[64 * 68];
    float* As = shm;
    float* Bs = shm + 32 * 68;
    int m0 = blockIdx.y * 64, n0 = blockIdx.x * 64;
    int t  = threadIdx.x;
    int ty = t >> 4, tx = t & 15;
    float acc[4][4] = {};

    for (int kk = 0; kk < 256; kk += 32) {
#pragma unroll
        for (int l = 0; l < 8; l++) {
            int i = l * 256 + t;
            int m = i >> 5, k = i & 31;
            As[k * 68 + m] = g_o[(size_t)(m0 + m) * 256 + kk + k];
        }
#pragma unroll
        for (int l = 0; l < 8; l++) {
            int i = l * 256 + t;
            int k = i >> 6, nn = i & 63;
            Bs[k * 68 + nn] = B[(size_t)(kk + k) * 256 + n0 + nn];
        }
        __syncthreads();
#pragma unroll
        for (int k = 0; k < 32; k++) {
            float a[4], b[4];
            *(float4*)a = *(const float4*)&As[k * 68 + 4 * ty];
            *(float4*)b = *(const float4*)&Bs[k * 68 + 4 * tx];
#pragma unroll
            for (int ii = 0; ii < 4; ii++)
#pragma unroll
                for (int jj = 0; jj < 4; jj++)
                    acc[ii][jj] = fmaf(a[ii], b[jj], acc[ii][jj]);
        }
        __syncthreads();
    }

    float bsv[4];
    *(float4*)bsv = *(const float4*)&bias[n0 + 4 * tx];
#pragma unroll
    for (int ii = 0; ii < 4; ii++)
#pragma unroll
        for (int jj = 0; jj < 4; jj++)
            shm[(4 * ty + ii) * 68 + 4 * tx + jj] = acc[ii][jj] + bsv[jj];
    __syncthreads();

    int nimg  = m0 >> 12;
    int pbase = m0 & 4095;
#pragma unroll
    for (int l = 0; l < 16; l++) {
        int i  = l * 256 + t;
        int pl = i & 63, cl = i >> 6;
        out[((size_t)nimg * C + n0 + cl) * HW + pbase + pl] = shm[pl * 68 + cl];
    }
}

// ---------------------------------------------------------------------------
extern "C" void kernel_launch(void* const* d_in, const int* in_sizes, int n_in,
                              void* d_out, int out_size) {
    const float* x      = (const float*)d_in[0];
    const float* gamma  = (const float*)d_in[1];
    const float* beta   = (const float*)d_in[2];
    const float* qkv_w  = (const float*)d_in[3];
    const float* proj_w = (const float*)d_in[4];
    const float* proj_b = (const float*)d_in[5];
    float* out = (float*)d_out;

    cudaFuncSetAttribute(attn_mma,
                         cudaFuncAttributeMaxDynamicSharedMemorySize, SMEM_ATTN_B);

    bn_stats<<<256, 256>>>(x, gamma, beta);
    norm_transpose<<<dim3(128, 8, 4), dim3(32, 8)>>>(x);
    gemm_qkv<<<dim3(12, 256), 256>>>(qkv_w);
    attn_mma<<<dim3(32, 16), 128, SMEM_ATTN_B>>>();
    gemm_proj<<<dim3(4, 256), 256>>>(proj_w, proj_b, out);
}

// round 5
// speedup vs baseline: 1.6002x; 1.6002x over previous
#include <cuda_runtime.h>
#include <cuda_fp16.h>
#include <math.h>
#include <stdint.h>

#define N_IMG   4
#define C       256
#define HW      4096
#define THREE_C 768

// Scratch (device globals: allocation-free rule)
__device__ float g_scale[C];
__device__ float g_shift[C];
__device__ float g_seq[N_IMG * HW * C];        // normalized, (n, hw, c)
__device__ float g_qkv[N_IMG * HW * THREE_C];  // (n, hw, 3c)
__device__ float g_o[N_IMG * HW * C];          // attention output, (n, hw, c)

__device__ __forceinline__ uint32_t smem_u32(const void* p) {
    uint32_t a;
    asm("{ .reg .u64 t; cvta.to.shared.u64 t, %1; cvt.u32.u64 %0, t; }"
        : "=r"(a) : "l"(p));
    return a;
}
// pack two floats into half2 (lo, hi)
__device__ __forceinline__ uint32_t f2h2(float lo, float hi) {
    uint32_t u;
    asm("cvt.rn.f16x2.f32 %0, %1, %2;" : "=r"(u) : "f"(hi), "f"(lo));
    return u;
}
// m16n8k16 fp16 mma, fp32 accum (portable sm_80+ ISA)
__device__ __forceinline__ void mma16(float* d, const uint32_t* a,
                                      uint32_t b0, uint32_t b1) {
    asm volatile(
        "mma.sync.aligned.m16n8k16.row.col.f32.f16.f16.f32 "
        "{%0,%1,%2,%3}, {%4,%5,%6,%7}, {%8,%9}, {%0,%1,%2,%3};"
        : "+f"(d[0]), "+f"(d[1]), "+f"(d[2]), "+f"(d[3])
        : "r"(a[0]), "r"(a[1]), "r"(a[2]), "r"(a[3]), "r"(b0), "r"(b1));
}
__device__ __forceinline__ void ldsm4(uint32_t* r, uint32_t a) {
    asm volatile("ldmatrix.sync.aligned.m8n8.x4.shared.b16 {%0,%1,%2,%3}, [%4];"
                 : "=r"(r[0]), "=r"(r[1]), "=r"(r[2]), "=r"(r[3]) : "r"(a));
}
__device__ __forceinline__ void ldsm4t(uint32_t* r, uint32_t a) {
    asm volatile("ldmatrix.sync.aligned.m8n8.x4.trans.shared.b16 {%0,%1,%2,%3}, [%4];"
                 : "=r"(r[0]), "=r"(r[1]), "=r"(r[2]), "=r"(r[3]) : "r"(a));
}

// Shared byte offsets. Half tiles, pitch 72 halfs (144 B): bank = 4*row mod 32.
#define KSB 0                    // K: 64 x 72 half
#define VSB 9216                 // V: 64 x 72 half
#define PSB 18432                // P: 128 x 72 half
#define SMEM_ATTN_B 36864        // also reused as 128x68 float staging (34816 B)

// ===========================================================================
// fp16 m16n8k16 flash attention, no-max-subtraction softmax.
// Grid (32 q-tiles of 128, 16 n*h). 128 threads = 4 warps, 32 q-rows/warp.
// Faithful-reshape indexing: head-row r -> seq p = h*1024 + r/4, s = r%4;
// Q col 192s+d, K +64, V +128; output col 64s+d.
// ===========================================================================
__global__ __launch_bounds__(128) void attn_mma() {
    extern __shared__ char smraw[];
    const uint32_t sb = smem_u32(smraw);
    float* smf = (float*)smraw;

    const int t    = threadIdx.x;
    const int w    = t >> 5;
    const int lane = t & 31;
    const int g    = lane >> 2;
    const int tg   = lane & 3;
    const int rb   = w * 32;          // warp q-row base

    const int qt = blockIdx.x;
    const int nh = blockIdx.y;
    const int n  = nh >> 2, h = nh & 3;
    const float* qkv = g_qkv + (size_t)n * HW * THREE_C;

    const int d4 = (t & 15) * 4;      // loader column (float4)
    const int rl = t >> 4;            // loader row lane 0..7

    // ldmatrix per-lane base addresses (byte offsets, see fragment maps)
    const uint32_t sub = lane >> 3;
    const uint32_t kfb = sb + KSB + ((((sub >> 1) * 8) + (lane & 7)) * 72 + (sub & 1) * 8) * 2;
    const uint32_t vfb = sb + VSB + ((((sub & 1) * 8) + (lane & 7)) * 72 + (sub >> 1) * 8) * 2;
    const uint32_t pfb = sb + PSB + (((rb + (sub & 1) * 8) + (lane & 7)) * 72 + (sub >> 1) * 8) * 2;

    // ---- Q A-fragments in registers: aq[mt][ks][0..3] ----
    uint32_t aq[2][4][4];
#pragma unroll
    for (int mt = 0; mt < 2; mt++) {
#pragma unroll
        for (int rr = 0; rr < 2; rr++) {
            int r  = qt * 128 + rb + mt * 16 + rr * 8 + g;
            int p  = h * 1024 + (r >> 2);
            int s  = r & 3;
            const float* qrow = qkv + (size_t)p * 768 + s * 192;
#pragma unroll
            for (int ks = 0; ks < 4; ks++) {
                float2 lo = *(const float2*)&qrow[ks * 16 + 2 * tg];
                float2 hi = *(const float2*)&qrow[ks * 16 + 8 + 2 * tg];
                aq[mt][ks][rr]     = f2h2(lo.x, lo.y);
                aq[mt][ks][rr + 2] = f2h2(hi.x, hi.y);
            }
        }
    }

    float co[2][8][4] = {};
    float lsum[2][2]  = {};

    for (int kt = 0; kt < 64; kt++) {
        // ---- Load K, V tiles (64 x 64) as fp16 ----
#pragma unroll
        for (int i = 0; i < 8; i++) {
            int row = 8 * i + rl;
            int rg  = kt * 64 + row;
            int p   = h * 1024 + (rg >> 2);
            int s   = rg & 3;
            const float* base = &qkv[(size_t)p * 768 + s * 192];
            float4 kv = *(const float4*)&base[64 + d4];
            float4 vv = *(const float4*)&base[128 + d4];
            *(uint2*)(smraw + KSB + (row * 72 + d4) * 2) =
                make_uint2(f2h2(kv.x, kv.y), f2h2(kv.z, kv.w));
            *(uint2*)(smraw + VSB + (row * 72 + d4) * 2) =
                make_uint2(f2h2(vv.x, vv.y), f2h2(vv.z, vv.w));
        }
        __syncthreads();

        // ---- S = Q K^T (64 mmas/warp) ----
        float sc[2][8][4] = {};
#pragma unroll
        for (int ks = 0; ks < 4; ks++) {
#pragma unroll
            for (int ntp = 0; ntp < 4; ntp++) {
                uint32_t kb[4];
                ldsm4(kb, kfb + ntp * 2304 + ks * 32);
                mma16(sc[0][2 * ntp],     aq[0][ks], kb[0], kb[1]);
                mma16(sc[0][2 * ntp + 1], aq[0][ks], kb[2], kb[3]);
                mma16(sc[1][2 * ntp],     aq[1][ks], kb[0], kb[1]);
                mma16(sc[1][2 * ntp + 1], aq[1][ks], kb[2], kb[3]);
            }
        }

        // ---- softmax: exp(S/8), P -> smem fp16, partial row sums ----
#pragma unroll
        for (int mt = 0; mt < 2; mt++) {
            int r0 = rb + mt * 16 + g;
#pragma unroll
            for (int nt = 0; nt < 8; nt++) {
                float p0 = __expf(sc[mt][nt][0] * 0.125f);
                float p1 = __expf(sc[mt][nt][1] * 0.125f);
                float p2 = __expf(sc[mt][nt][2] * 0.125f);
                float p3 = __expf(sc[mt][nt][3] * 0.125f);
                lsum[mt][0] += p0 + p1;
                lsum[mt][1] += p2 + p3;
                *(uint32_t*)(smraw + PSB + (r0 * 72 + nt * 8 + 2 * tg) * 2) =
                    f2h2(p0, p1);
                *(uint32_t*)(smraw + PSB + ((r0 + 8) * 72 + nt * 8 + 2 * tg) * 2) =
                    f2h2(p2, p3);
            }
        }
        __syncwarp();

        // ---- O += P V (64 mmas/warp) ----
#pragma unroll
        for (int ks = 0; ks < 4; ks++) {
            uint32_t pa0[4], pa1[4];
            ldsm4(pa0, pfb + ks * 32);
            ldsm4(pa1, pfb + 2304 + ks * 32);
#pragma unroll
            for (int ntp = 0; ntp < 4; ntp++) {
                uint32_t vb[4];
                ldsm4t(vb, vfb + ks * 2304 + ntp * 32);
                mma16(co[0][2 * ntp],     pa0, vb[0], vb[1]);
                mma16(co[0][2 * ntp + 1], pa0, vb[2], vb[3]);
                mma16(co[1][2 * ntp],     pa1, vb[0], vb[1]);
                mma16(co[1][2 * ntp + 1], pa1, vb[2], vb[3]);
            }
        }
        __syncthreads();
    }

    // ---- finalize: quad row-sum reduce, normalize, stage as fp32, store ----
    float inv[2][2];
#pragma unroll
    for (int mt = 0; mt < 2; mt++)
#pragma unroll
        for (int hh = 0; hh < 2; hh++) {
            float l = lsum[mt][hh];
            l += __shfl_xor_sync(0xffffffffu, l, 1);
            l += __shfl_xor_sync(0xffffffffu, l, 2);
            inv[mt][hh] = 1.f / l;
        }
#pragma unroll
    for (int mt = 0; mt < 2; mt++) {
        int r0 = rb + mt * 16 + g;
#pragma unroll
        for (int nt = 0; nt < 8; nt++) {
            smf[r0 * 68 + nt * 8 + 2 * tg]           = co[mt][nt][0] * inv[mt][0];
            smf[r0 * 68 + nt * 8 + 2 * tg + 1]       = co[mt][nt][1] * inv[mt][0];
            smf[(r0 + 8) * 68 + nt * 8 + 2 * tg]     = co[mt][nt][2] * inv[mt][1];
            smf[(r0 + 8) * 68 + nt * 8 + 2 * tg + 1] = co[mt][nt][3] * inv[mt][1];
        }
    }
    __syncthreads();
    {
        int rg = qt * 128 + t;
        int p  = h * 1024 + (rg >> 2);
        int s  = rg & 3;
        float* dst = g_o + ((size_t)n * HW + p) * C + s * 64;
#pragma unroll
        for (int i = 0; i < 16; i++)
            *(float4*)&dst[4 * i] = *(float4*)&smf[t * 68 + 4 * i];
    }
}

// ---------------------------------------------------------------------------
// 1) BatchNorm statistics -> per-channel scale/shift
// ---------------------------------------------------------------------------
__global__ void bn_stats(const float* __restrict__ x,
                         const float* __restrict__ gamma,
                         const float* __restrict__ beta) {
    int c = blockIdx.x;
    int t = threadIdx.x;
    float s = 0.f, s2 = 0.f;
    for (int n = 0; n < N_IMG; n++) {
        const float* p = x + ((size_t)n * C + c) * HW;
        for (int i = t; i < HW; i += 256) {
            float v = p[i];
            s += v;
            s2 += v * v;
        }
    }
    __shared__ float sh0[256], sh1[256];
    sh0[t] = s; sh1[t] = s2;
    __syncthreads();
    for (int o = 128; o > 0; o >>= 1) {
        if (t < o) { sh0[t] += sh0[t + o]; sh1[t] += sh1[t + o]; }
        __syncthreads();
    }
    if (t == 0) {
        const float inv = 1.f / (float)(N_IMG * HW);
        float mean = sh0[0] * inv;
        float var  = sh1[0] * inv - mean * mean;
        float rstd = rsqrtf(var + 1e-5f);
        float sc   = gamma[c] * rstd;
        g_scale[c] = sc;
        g_shift[c] = beta[c] - mean * sc;
    }
}

// ---------------------------------------------------------------------------
// 2) Normalize + transpose (n,c,hw) -> (n,hw,c)
// ---------------------------------------------------------------------------
__global__ void norm_transpose(const float* __restrict__ x) {
    __shared__ float tile[32][33];
    int n  = blockIdx.z;
    int c0 = blockIdx.y * 32;
    int p0 = blockIdx.x * 32;
    int tx = threadIdx.x, ty = threadIdx.y;  // 32 x 8
#pragma unroll
    for (int j = 0; j < 4; j++) {
        int c = c0 + ty + j * 8;
        tile[ty + j * 8][tx] =
            x[((size_t)n * C + c) * HW + p0 + tx] * g_scale[c] + g_shift[c];
    }
    __syncthreads();
#pragma unroll
    for (int j = 0; j < 4; j++) {
        int p = p0 + ty + j * 8;
        g_seq[((size_t)n * HW + p) * C + c0 + tx] = tile[tx][ty + j * 8];
    }
}

// ---------------------------------------------------------------------------
// 3) QKV GEMM: (16384 x 256) @ (256 x 768) -> g_qkv
// ---------------------------------------------------------------------------
__global__ __launch_bounds__(256) void gemm_qkv(const float* __restrict__ B) {
    __shared__ float As[32 * 68];
    __shared__ float Bs[32 * 68];
    int m0 = blockIdx.y * 64, n0 = blockIdx.x * 64;
    int t  = threadIdx.x;
    int ty = t >> 4, tx = t & 15;
    float acc[4][4] = {};

    for (int kk = 0; kk < 256; kk += 32) {
#pragma unroll
        for (int l = 0; l < 8; l++) {
            int i = l * 256 + t;
            int m = i >> 5, k = i & 31;
            As[k * 68 + m] = g_seq[(size_t)(m0 + m) * 256 + kk + k];
        }
#pragma unroll
        for (int l = 0; l < 8; l++) {
            int i = l * 256 + t;
            int k = i >> 6, nn = i & 63;
            Bs[k * 68 + nn] = B[(size_t)(kk + k) * 768 + n0 + nn];
        }
        __syncthreads();
#pragma unroll
        for (int k = 0; k < 32; k++) {
            float a[4], b[4];
            *(float4*)a = *(const float4*)&As[k * 68 + 4 * ty];
            *(float4*)b = *(const float4*)&Bs[k * 68 + 4 * tx];
#pragma unroll
            for (int ii = 0; ii < 4; ii++)
#pragma unroll
                for (int jj = 0; jj < 4; jj++)
                    acc[ii][jj] = fmaf(a[ii], b[jj], acc[ii][jj]);
        }
        __syncthreads();
    }
#pragma unroll
    for (int ii = 0; ii < 4; ii++) {
        float4 v = make_float4(acc[ii][0], acc[ii][1], acc[ii][2], acc[ii][3]);
        *(float4*)&g_qkv[(size_t)(m0 + 4 * ty + ii) * 768 + n0 + 4 * tx] = v;
    }
}

// ---------------------------------------------------------------------------
// 5) Proj GEMM: (16384 x 256) @ (256 x 256) + b -> out (n,c,h,w)
// ---------------------------------------------------------------------------
__global__ __launch_bounds__(256) void gemm_proj(const float* __restrict__ B,
                                                 const float* __restrict__ bias,
                                                 float* __restrict__ out) {
    __shared__ float shm[64 * 68];
    float* As = shm;
    float* Bs = shm + 32 * 68;
    int m0 = blockIdx.y * 64, n0 = blockIdx.x * 64;
    int t  = threadIdx.x;
    int ty = t >> 4, tx = t & 15;
    float acc[4][4] = {};

    for (int kk = 0; kk < 256; kk += 32) {
#pragma unroll
        for (int l = 0; l < 8; l++) {
            int i = l * 256 + t;
            int m = i >> 5, k = i & 31;
            As[k * 68 + m] = g_o[(size_t)(m0 + m) * 256 + kk + k];
        }
#pragma unroll
        for (int l = 0; l < 8; l++) {
            int i = l * 256 + t;
            int k = i >> 6, nn = i & 63;
            Bs[k * 68 + nn] = B[(size_t)(kk + k) * 256 + n0 + nn];
        }
        __syncthreads();
#pragma unroll
        for (int k = 0; k < 32; k++) {
            float a[4], b[4];
            *(float4*)a = *(const float4*)&As[k * 68 + 4 * ty];
            *(float4*)b = *(const float4*)&Bs[k * 68 + 4 * tx];
#pragma unroll
            for (int ii = 0; ii < 4; ii++)
#pragma unroll
                for (int jj = 0; jj < 4; jj++)
                    acc[ii][jj] = fmaf(a[ii], b[jj], acc[ii][jj]);
        }
        __syncthreads();
    }

    float bsv[4];
    *(float4*)bsv = *(const float4*)&bias[n0 + 4 * tx];
#pragma unroll
    for (int ii = 0; ii < 4; ii++)
#pragma unroll
        for (int jj = 0; jj < 4; jj++)
            shm[(4 * ty + ii) * 68 + 4 * tx + jj] = acc[ii][jj] + bsv[jj];
    __syncthreads();

    int nimg  = m0 >> 12;
    int pbase = m0 & 4095;
#pragma unroll
    for (int l = 0; l < 16; l++) {
        int i  = l * 256 + t;
        int pl = i & 63, cl = i >> 6;
        out[((size_t)nimg * C + n0 + cl) * HW + pbase + pl] = shm[pl * 68 + cl];
    }
}

// ---------------------------------------------------------------------------
extern "C" void kernel_launch(void* const* d_in, const int* in_sizes, int n_in,
                              void* d_out, int out_size) {
    const float* x      = (const float*)d_in[0];
    const float* gamma  = (const float*)d_in[1];
    const float* beta   = (const float*)d_in[2];
    const float* qkv_w  = (const float*)d_in[3];
    const float* proj_w = (const float*)d_in[4];
    const float* proj_b = (const float*)d_in[5];
    float* out = (float*)d_out;

    bn_stats<<<256, 256>>>(x, gamma, beta);
    norm_transpose<<<dim3(128, 8, 4), dim3(32, 8)>>>(x);
    gemm_qkv<<<dim3(12, 256), 256>>>(qkv_w);
    attn_mma<<<dim3(32, 16), 128, SMEM_ATTN_B>>>();
    gemm_proj<<<dim3(4, 256), 256>>>(proj_w, proj_b, out);
}

// round 6
// speedup vs baseline: 2.5966x; 1.6227x over previous
#include <cuda_runtime.h>
#include <cuda_fp16.h>
#include <math.h>
#include <stdint.h>

#define N_IMG   4
#define C       256
#define HW      4096
#define THREE_C 768

// Scratch (device globals: allocation-free rule)
__device__ float g_scale[C];
__device__ float g_shift[C];
__device__ __align__(16) __half g_seq_h[N_IMG * HW * C];
__device__ __align__(16) __half g_qkv_h[N_IMG * HW * THREE_C];
__device__ __align__(16) __half g_o_h[N_IMG * HW * C];
__device__ __align__(16) __half g_wq_h[C * THREE_C];
__device__ __align__(16) __half g_wp_h[C * C];

__device__ __forceinline__ uint32_t smem_u32(const void* p) {
    uint32_t a;
    asm("{ .reg .u64 t; cvta.to.shared.u64 t, %1; cvt.u32.u64 %0, t; }"
        : "=r"(a) : "l"(p));
    return a;
}
__device__ __forceinline__ uint32_t f2h2(float lo, float hi) {
    uint32_t u;
    asm("cvt.rn.f16x2.f32 %0, %1, %2;" : "=r"(u) : "f"(hi), "f"(lo));
    return u;
}
__device__ __forceinline__ void mma16(float* d, const uint32_t* a,
                                      uint32_t b0, uint32_t b1) {
    asm volatile(
        "mma.sync.aligned.m16n8k16.row.col.f32.f16.f16.f32 "
        "{%0,%1,%2,%3}, {%4,%5,%6,%7}, {%8,%9}, {%0,%1,%2,%3};"
        : "+f"(d[0]), "+f"(d[1]), "+f"(d[2]), "+f"(d[3])
        : "r"(a[0]), "r"(a[1]), "r"(a[2]), "r"(a[3]), "r"(b0), "r"(b1));
}
__device__ __forceinline__ void ldsm4(uint32_t* r, uint32_t a) {
    asm volatile("ldmatrix.sync.aligned.m8n8.x4.shared.b16 {%0,%1,%2,%3}, [%4];"
                 : "=r"(r[0]), "=r"(r[1]), "=r"(r[2]), "=r"(r[3]) : "r"(a));
}
__device__ __forceinline__ void ldsm4t(uint32_t* r, uint32_t a) {
    asm volatile("ldmatrix.sync.aligned.m8n8.x4.trans.shared.b16 {%0,%1,%2,%3}, [%4];"
                 : "=r"(r[0]), "=r"(r[1]), "=r"(r[2]), "=r"(r[3]) : "r"(a));
}

// ===========================================================================
// fp16 GEMM core: BM=128, BN=128, BK=32, 256 threads (8 warps, 4m x 2n),
// warp tile 32x64. A [m][k] row-major half, B [k][n] row-major half.
// ===========================================================================
#define GA_PITCH 40
#define GB_PITCH 136
#define GB_OFF   (128 * GA_PITCH * 2)                // 10240 bytes
#define GEMM_SMEM (GB_OFF + 32 * GB_PITCH * 2)       // 18944 bytes
#define PJ_SMEM  (128 * 132 * 4)                     // 67584 bytes (proj staging)

// ---- QKV GEMM: (16384 x 256) @ (256 x 768) -> g_qkv_h ----
__global__ __launch_bounds__(256) void gemm_qkv_h() {
    __shared__ __align__(16) char smem[GEMM_SMEM];
    const uint32_t sb = smem_u32(smem);
    const int t = threadIdx.x, w = t >> 5, lane = t & 31;
    const int sub = lane >> 3, g = lane >> 2, tg = lane & 3;
    const int wr = w >> 1, wc = w & 1;
    const int m0 = blockIdx.y * 128, n0 = blockIdx.x * 128;

    const uint32_t abase = sb +
        ((wr * 32 + (sub & 1) * 8 + (lane & 7)) * GA_PITCH + (sub >> 1) * 8) * 2;
    const uint32_t bbase = sb + GB_OFF +
        (((sub & 1) * 8 + (lane & 7)) * GB_PITCH + wc * 64 + (sub >> 1) * 8) * 2;

    const __half* Ag = g_seq_h + (size_t)m0 * 256;
    const int arow = t >> 1, acq = (t & 1) * 16;
    const int brow = t >> 3, bcq = (t & 7) * 16;

    float acc[2][8][4] = {};
    for (int kk = 0; kk < 256; kk += 32) {
        *(uint4*)(smem + (arow * GA_PITCH + acq) * 2) =
            *(const uint4*)&Ag[arow * 256 + kk + acq];
        *(uint4*)(smem + (arow * GA_PITCH + acq + 8) * 2) =
            *(const uint4*)&Ag[arow * 256 + kk + acq + 8];
        *(uint4*)(smem + GB_OFF + (brow * GB_PITCH + bcq) * 2) =
            *(const uint4*)&g_wq_h[(kk + brow) * 768 + n0 + bcq];
        *(uint4*)(smem + GB_OFF + (brow * GB_PITCH + bcq + 8) * 2) =
            *(const uint4*)&g_wq_h[(kk + brow) * 768 + n0 + bcq + 8];
        __syncthreads();
#pragma unroll
        for (int ks = 0; ks < 2; ks++) {
            uint32_t a0[4], a1[4];
            ldsm4(a0, abase + ks * 32);
            ldsm4(a1, abase + 16 * GA_PITCH * 2 + ks * 32);
#pragma unroll
            for (int ntp = 0; ntp < 4; ntp++) {
                uint32_t vb[4];
                ldsm4t(vb, bbase + ks * 16 * GB_PITCH * 2 + ntp * 32);
                mma16(acc[0][2 * ntp],     a0, vb[0], vb[1]);
                mma16(acc[0][2 * ntp + 1], a0, vb[2], vb[3]);
                mma16(acc[1][2 * ntp],     a1, vb[0], vb[1]);
                mma16(acc[1][2 * ntp + 1], a1, vb[2], vb[3]);
            }
        }
        __syncthreads();
    }
#pragma unroll
    for (int mt = 0; mt < 2; mt++)
#pragma unroll
        for (int nt = 0; nt < 8; nt++) {
            int row = m0 + wr * 32 + mt * 16 + g;
            int col = n0 + wc * 64 + nt * 8 + 2 * tg;
            *(uint32_t*)&g_qkv_h[(size_t)row * 768 + col] =
                f2h2(acc[mt][nt][0], acc[mt][nt][1]);
            *(uint32_t*)&g_qkv_h[(size_t)(row + 8) * 768 + col] =
                f2h2(acc[mt][nt][2], acc[mt][nt][3]);
        }
}

// ---- Proj GEMM: (16384 x 256) @ (256 x 256) + b -> out NCHW (transposed) ----
__global__ __launch_bounds__(256) void gemm_proj_h(const float* __restrict__ bias,
                                                   float* __restrict__ out) {
    extern __shared__ __align__(16) char smem[];
    const uint32_t sb = smem_u32(smem);
    const int t = threadIdx.x, w = t >> 5, lane = t & 31;
    const int sub = lane >> 3, g = lane >> 2, tg = lane & 3;
    const int wr = w >> 1, wc = w & 1;
    const int m0 = blockIdx.y * 128, n0 = blockIdx.x * 128;

    const uint32_t abase = sb +
        ((wr * 32 + (sub & 1) * 8 + (lane & 7)) * GA_PITCH + (sub >> 1) * 8) * 2;
    const uint32_t bbase = sb + GB_OFF +
        (((sub & 1) * 8 + (lane & 7)) * GB_PITCH + wc * 64 + (sub >> 1) * 8) * 2;

    const __half* Ag = g_o_h + (size_t)m0 * 256;
    const int arow = t >> 1, acq = (t & 1) * 16;
    const int brow = t >> 3, bcq = (t & 7) * 16;

    float acc[2][8][4] = {};
    for (int kk = 0; kk < 256; kk += 32) {
        *(uint4*)(smem + (arow * GA_PITCH + acq) * 2) =
            *(const uint4*)&Ag[arow * 256 + kk + acq];
        *(uint4*)(smem + (arow * GA_PITCH + acq + 8) * 2) =
            *(const uint4*)&Ag[arow * 256 + kk + acq + 8];
        *(uint4*)(smem + GB_OFF + (brow * GB_PITCH + bcq) * 2) =
            *(const uint4*)&g_wp_h[(kk + brow) * 256 + n0 + bcq];
        *(uint4*)(smem + GB_OFF + (brow * GB_PITCH + bcq + 8) * 2) =
            *(const uint4*)&g_wp_h[(kk + brow) * 256 + n0 + bcq + 8];
        __syncthreads();
#pragma unroll
        for (int ks = 0; ks < 2; ks++) {
            uint32_t a0[4], a1[4];
            ldsm4(a0, abase + ks * 32);
            ldsm4(a1, abase + 16 * GA_PITCH * 2 + ks * 32);
#pragma unroll
            for (int ntp = 0; ntp < 4; ntp++) {
                uint32_t vb[4];
                ldsm4t(vb, bbase + ks * 16 * GB_PITCH * 2 + ntp * 32);
                mma16(acc[0][2 * ntp],     a0, vb[0], vb[1]);
                mma16(acc[0][2 * ntp + 1], a0, vb[2], vb[3]);
                mma16(acc[1][2 * ntp],     a1, vb[0], vb[1]);
                mma16(acc[1][2 * ntp + 1], a1, vb[2], vb[3]);
            }
        }
        __syncthreads();
    }

    // stage [c][m+pad] fp32 for coalesced transposed store
    float* st = (float*)smem;
#pragma unroll
    for (int mt = 0; mt < 2; mt++)
#pragma unroll
        for (int nt = 0; nt < 8; nt++) {
            int rl = wr * 32 + mt * 16 + g;
            int cl = wc * 64 + nt * 8 + 2 * tg;
            st[cl * 132 + rl]           = acc[mt][nt][0];
            st[(cl + 1) * 132 + rl]     = acc[mt][nt][1];
            st[cl * 132 + rl + 8]       = acc[mt][nt][2];
            st[(cl + 1) * 132 + rl + 8] = acc[mt][nt][3];
        }
    __syncthreads();

    const int ml = t & 31, wi = t >> 5;
    const int nimg = m0 >> 12, pbase = m0 & 4095;
#pragma unroll
    for (int i = 0; i < 16; i++) {
        int cl = wi + 8 * i;
        float bb = bias[n0 + cl];
        float* orow = out + ((size_t)(nimg * C + n0 + cl)) * HW + pbase;
#pragma unroll
        for (int ch = 0; ch < 4; ch++)
            orow[ml + 32 * ch] = st[cl * 132 + ml + 32 * ch] + bb;
    }
}

// ===========================================================================
// fp16 flash attention (unchanged math from R5; half I/O, no in-loop cvt)
// ===========================================================================
#define KSB 0
#define VSB 9216
#define PSB 18432
#define SMEM_ATTN_B 36864

__global__ __launch_bounds__(128) void attn_mma() {
    extern __shared__ char smraw[];
    const uint32_t sb = smem_u32(smraw);

    const int t    = threadIdx.x;
    const int w    = t >> 5;
    const int lane = t & 31;
    const int g    = lane >> 2;
    const int tg   = lane & 3;
    const int rb   = w * 32;

    const int qt = blockIdx.x;
    const int nh = blockIdx.y;
    const int n  = nh >> 2, h = nh & 3;
    const __half* qkvh = g_qkv_h + (size_t)n * HW * THREE_C;

    const int c4 = (t & 15) * 4;      // loader column (4 halfs)
    const int rl = t >> 4;            // loader row lane 0..7

    const uint32_t sub = lane >> 3;
    const uint32_t kfb = sb + KSB + ((((sub >> 1) * 8) + (lane & 7)) * 72 + (sub & 1) * 8) * 2;
    const uint32_t vfb = sb + VSB + ((((sub & 1) * 8) + (lane & 7)) * 72 + (sub >> 1) * 8) * 2;
    const uint32_t pfb = sb + PSB + (((rb + (sub & 1) * 8) + (lane & 7)) * 72 + (sub >> 1) * 8) * 2;

    // Q A-frags in registers (direct half2 loads)
    uint32_t aq[2][4][4];
#pragma unroll
    for (int mt = 0; mt < 2; mt++)
#pragma unroll
        for (int rr = 0; rr < 2; rr++) {
            int r  = qt * 128 + rb + mt * 16 + rr * 8 + g;
            int p  = h * 1024 + (r >> 2);
            int s  = r & 3;
            const __half* qrow = qkvh + (size_t)p * 768 + s * 192;
#pragma unroll
            for (int ks = 0; ks < 4; ks++) {
                aq[mt][ks][rr]     = *(const uint32_t*)&qrow[ks * 16 + 2 * tg];
                aq[mt][ks][rr + 2] = *(const uint32_t*)&qrow[ks * 16 + 8 + 2 * tg];
            }
        }

    float co[2][8][4] = {};
    float lsum[2][2]  = {};

    for (int kt = 0; kt < 64; kt++) {
#pragma unroll
        for (int i = 0; i < 8; i++) {
            int row = 8 * i + rl;
            int rg  = kt * 64 + row;
            int p   = h * 1024 + (rg >> 2);
            int s   = rg & 3;
            const __half* base = qkvh + (size_t)p * 768 + s * 192;
            *(uint2*)(smraw + KSB + (row * 72 + c4) * 2) = *(const uint2*)&base[64 + c4];
            *(uint2*)(smraw + VSB + (row * 72 + c4) * 2) = *(const uint2*)&base[128 + c4];
        }
        __syncthreads();

        float sc[2][8][4] = {};
#pragma unroll
        for (int ks = 0; ks < 4; ks++) {
#pragma unroll
            for (int ntp = 0; ntp < 4; ntp++) {
                uint32_t kb[4];
                ldsm4(kb, kfb + ntp * 2304 + ks * 32);
                mma16(sc[0][2 * ntp],     aq[0][ks], kb[0], kb[1]);
                mma16(sc[0][2 * ntp + 1], aq[0][ks], kb[2], kb[3]);
                mma16(sc[1][2 * ntp],     aq[1][ks], kb[0], kb[1]);
                mma16(sc[1][2 * ntp + 1], aq[1][ks], kb[2], kb[3]);
            }
        }

#pragma unroll
        for (int mt = 0; mt < 2; mt++) {
            int r0 = rb + mt * 16 + g;
#pragma unroll
            for (int nt = 0; nt < 8; nt++) {
                float p0 = __expf(sc[mt][nt][0] * 0.125f);
                float p1 = __expf(sc[mt][nt][1] * 0.125f);
                float p2 = __expf(sc[mt][nt][2] * 0.125f);
                float p3 = __expf(sc[mt][nt][3] * 0.125f);
                lsum[mt][0] += p0 + p1;
                lsum[mt][1] += p2 + p3;
                *(uint32_t*)(smraw + PSB + (r0 * 72 + nt * 8 + 2 * tg) * 2) = f2h2(p0, p1);
                *(uint32_t*)(smraw + PSB + ((r0 + 8) * 72 + nt * 8 + 2 * tg) * 2) = f2h2(p2, p3);
            }
        }
        __syncwarp();

#pragma unroll
        for (int ks = 0; ks < 4; ks++) {
            uint32_t pa0[4], pa1[4];
            ldsm4(pa0, pfb + ks * 32);
            ldsm4(pa1, pfb + 2304 + ks * 32);
#pragma unroll
            for (int ntp = 0; ntp < 4; ntp++) {
                uint32_t vb[4];
                ldsm4t(vb, vfb + ks * 2304 + ntp * 32);
                mma16(co[0][2 * ntp],     pa0, vb[0], vb[1]);
                mma16(co[0][2 * ntp + 1], pa0, vb[2], vb[3]);
                mma16(co[1][2 * ntp],     pa1, vb[0], vb[1]);
                mma16(co[1][2 * ntp + 1], pa1, vb[2], vb[3]);
            }
        }
        __syncthreads();
    }

    // finalize: quad row-sum reduce, normalize, stage as half, store
    float inv[2][2];
#pragma unroll
    for (int mt = 0; mt < 2; mt++)
#pragma unroll
        for (int hh = 0; hh < 2; hh++) {
            float l = lsum[mt][hh];
            l += __shfl_xor_sync(0xffffffffu, l, 1);
            l += __shfl_xor_sync(0xffffffffu, l, 2);
            inv[mt][hh] = 1.f / l;
        }
    __syncthreads();   // done with K/V/P smem; reuse as half staging [128][80]
#pragma unroll
    for (int mt = 0; mt < 2; mt++) {
        int r0 = rb + mt * 16 + g;
#pragma unroll
        for (int nt = 0; nt < 8; nt++) {
            *(uint32_t*)(smraw + (r0 * 80 + nt * 8 + 2 * tg) * 2) =
                f2h2(co[mt][nt][0] * inv[mt][0], co[mt][nt][1] * inv[mt][0]);
            *(uint32_t*)(smraw + ((r0 + 8) * 80 + nt * 8 + 2 * tg) * 2) =
                f2h2(co[mt][nt][2] * inv[mt][1], co[mt][nt][3] * inv[mt][1]);
        }
    }
    __syncthreads();
    {
        int rg = qt * 128 + t;
        int p  = h * 1024 + (rg >> 2);
        int s  = rg & 3;
        __half* dst = g_o_h + ((size_t)n * HW + p) * C + s * 64;
#pragma unroll
        for (int j = 0; j < 8; j++)
            *(uint4*)&dst[8 * j] = *(uint4*)(smraw + (t * 80 + 8 * j) * 2);
    }
}

// ---------------------------------------------------------------------------
// BatchNorm statistics -> per-channel scale/shift
// ---------------------------------------------------------------------------
__global__ void bn_stats(const float* __restrict__ x,
                         const float* __restrict__ gamma,
                         const float* __restrict__ beta) {
    int c = blockIdx.x;
    int t = threadIdx.x;
    float s = 0.f, s2 = 0.f;
    for (int n = 0; n < N_IMG; n++) {
        const float* p = x + ((size_t)n * C + c) * HW;
        for (int i = t; i < HW; i += 256) {
            float v = p[i];
            s += v;
            s2 += v * v;
        }
    }
    __shared__ float sh0[256], sh1[256];
    sh0[t] = s; sh1[t] = s2;
    __syncthreads();
    for (int o = 128; o > 0; o >>= 1) {
        if (t < o) { sh0[t] += sh0[t + o]; sh1[t] += sh1[t + o]; }
        __syncthreads();
    }
    if (t == 0) {
        const float inv = 1.f / (float)(N_IMG * HW);
        float mean = sh0[0] * inv;
        float var  = sh1[0] * inv - mean * mean;
        float rstd = rsqrtf(var + 1e-5f);
        float sc   = gamma[c] * rstd;
        g_scale[c] = sc;
        g_shift[c] = beta[c] - mean * sc;
    }
}

// ---------------------------------------------------------------------------
// Normalize + transpose (n,c,hw) -> (n,hw,c) as half
// ---------------------------------------------------------------------------
__global__ void norm_transpose(const float* __restrict__ x) {
    __shared__ float tile[32][33];
    int n  = blockIdx.z;
    int c0 = blockIdx.y * 32;
    int p0 = blockIdx.x * 32;
    int tx = threadIdx.x, ty = threadIdx.y;  // 32 x 8
#pragma unroll
    for (int j = 0; j < 4; j++) {
        int c = c0 + ty + j * 8;
        tile[ty + j * 8][tx] =
            x[((size_t)n * C + c) * HW + p0 + tx] * g_scale[c] + g_shift[c];
    }
    __syncthreads();
#pragma unroll
    for (int j = 0; j < 4; j++) {
        int p = p0 + ty + j * 8;
        g_seq_h[((size_t)n * HW + p) * C + c0 + tx] = __float2half_rn(tile[tx][ty + j * 8]);
    }
}

// ---------------------------------------------------------------------------
// Weight pre-conversion (once per launch; deterministic)
// ---------------------------------------------------------------------------
__global__ void convert_w(const float* __restrict__ qkv_w,
                          const float* __restrict__ proj_w) {
    int i = blockIdx.x * 256 + threadIdx.x;
    if (i < C * THREE_C) g_wq_h[i] = __float2half_rn(qkv_w[i]);
    int j = i - C * THREE_C;
    if (j >= 0 && j < C * C) g_wp_h[j] = __float2half_rn(proj_w[j]);
}

// ---------------------------------------------------------------------------
extern "C" void kernel_launch(void* const* d_in, const int* in_sizes, int n_in,
                              void* d_out, int out_size) {
    const float* x      = (const float*)d_in[0];
    const float* gamma  = (const float*)d_in[1];
    const float* beta   = (const float*)d_in[2];
    const float* qkv_w  = (const float*)d_in[3];
    const float* proj_w = (const float*)d_in[4];
    const float* proj_b = (const float*)d_in[5];
    float* out = (float*)d_out;

    cudaFuncSetAttribute(gemm_proj_h,
                         cudaFuncAttributeMaxDynamicSharedMemorySize, PJ_SMEM);

    bn_stats<<<256, 256>>>(x, gamma, beta);
    norm_transpose<<<dim3(128, 8, 4), dim3(32, 8)>>>(x);
    convert_w<<<(C * THREE_C + C * C) / 256, 256>>>(qkv_w, proj_w);
    gemm_qkv_h<<<dim3(6, 128), 256>>>();
    attn_mma<<<dim3(32, 16), 128, SMEM_ATTN_B>>>();
    gemm_proj_h<<<dim3(2, 128), 256, PJ_SMEM>>>(proj_b, out);
}

// round 7
// speedup vs baseline: 3.0293x; 1.1666x over previous
#include <cuda_runtime.h>
#include <cuda_fp16.h>
#include <math.h>
#include <stdint.h>

#define N_IMG   4
#define C       256
#define HW      4096
#define THREE_C 768

// Scratch (device globals: allocation-free rule)
__device__ float g_scale[C];
__device__ float g_shift[C];
__device__ __align__(16) __half g_seq_h[N_IMG * HW * C];
__device__ __align__(16) __half g_qkv_h[N_IMG * HW * THREE_C];
__device__ __align__(16) __half g_o_h[N_IMG * HW * C];
__device__ __align__(16) __half g_wq_h[C * THREE_C];
__device__ __align__(16) __half g_wp_h[C * C];

__device__ __forceinline__ uint32_t smem_u32(const void* p) {
    uint32_t a;
    asm("{ .reg .u64 t; cvta.to.shared.u64 t, %1; cvt.u32.u64 %0, t; }"
        : "=r"(a) : "l"(p));
    return a;
}
__device__ __forceinline__ uint32_t f2h2(float lo, float hi) {
    uint32_t u;
    asm("cvt.rn.f16x2.f32 %0, %1, %2;" : "=r"(u) : "f"(hi), "f"(lo));
    return u;
}
__device__ __forceinline__ void mma16(float* d, const uint32_t* a,
                                      uint32_t b0, uint32_t b1) {
    asm volatile(
        "mma.sync.aligned.m16n8k16.row.col.f32.f16.f16.f32 "
        "{%0,%1,%2,%3}, {%4,%5,%6,%7}, {%8,%9}, {%0,%1,%2,%3};"
        : "+f"(d[0]), "+f"(d[1]), "+f"(d[2]), "+f"(d[3])
        : "r"(a[0]), "r"(a[1]), "r"(a[2]), "r"(a[3]), "r"(b0), "r"(b1));
}
__device__ __forceinline__ void ldsm4(uint32_t* r, uint32_t a) {
    asm volatile("ldmatrix.sync.aligned.m8n8.x4.shared.b16 {%0,%1,%2,%3}, [%4];"
                 : "=r"(r[0]), "=r"(r[1]), "=r"(r[2]), "=r"(r[3]) : "r"(a));
}
__device__ __forceinline__ void ldsm4t(uint32_t* r, uint32_t a) {
    asm volatile("ldmatrix.sync.aligned.m8n8.x4.trans.shared.b16 {%0,%1,%2,%3}, [%4];"
                 : "=r"(r[0]), "=r"(r[1]), "=r"(r[2]), "=r"(r[3]) : "r"(a));
}
__device__ __forceinline__ void cpa16(uint32_t dst, const void* src) {
    asm volatile("cp.async.ca.shared.global [%0], [%1], 16;"
                 :: "r"(dst), "l"(src));
}
#define CPA_COMMIT() asm volatile("cp.async.commit_group;" ::: "memory")
#define CPA_WAIT1()  asm volatile("cp.async.wait_group 1;" ::: "memory")
#define CPA_WAIT0()  asm volatile("cp.async.wait_group 0;" ::: "memory")

// ===========================================================================
// fp16 GEMM core: BM=128, BN=128, BK=32, 256 threads (8 warps, 4m x 2n),
// 3-stage cp.async pipeline, ONE barrier per k-iteration.
// ===========================================================================
#define GA_PITCH 40
#define GB_PITCH 136
#define GB_OFF   (128 * GA_PITCH * 2)                // 10240 B (A stage)
#define GST      (GB_OFF + 32 * GB_PITCH * 2)        // 18944 B per stage
#define QK_SMEM  (3 * GST)                           // 56832 B
#define PJ_SMEM  (128 * 132 * 4)                     // 67584 B (proj staging)

// ---- QKV GEMM: (16384 x 256) @ (256 x 768) -> g_qkv_h ----
__global__ __launch_bounds__(256) void gemm_qkv_h() {
    extern __shared__ __align__(16) char smem[];
    const uint32_t sb = smem_u32(smem);
    const int t = threadIdx.x, w = t >> 5, lane = t & 31;
    const int sub = lane >> 3, g = lane >> 2, tg = lane & 3;
    const int wr = w >> 1, wc = w & 1;
    const int m0 = blockIdx.y * 128, n0 = blockIdx.x * 128;

    const uint32_t a_off =
        ((wr * 32 + (sub & 1) * 8 + (lane & 7)) * GA_PITCH + (sub >> 1) * 8) * 2;
    const uint32_t b_off = GB_OFF +
        (((sub & 1) * 8 + (lane & 7)) * GB_PITCH + wc * 64 + (sub >> 1) * 8) * 2;

    const __half* Ag = g_seq_h + (size_t)m0 * 256;
    const int arow = t >> 1, acq = (t & 1) * 16;
    const int brow = t >> 3, bcq = (t & 7) * 16;

#define QKV_COPY(stg, kk)                                                      \
    do {                                                                       \
        uint32_t sbase = sb + (stg) * GST;                                     \
        cpa16(sbase + (arow * GA_PITCH + acq) * 2,                             \
              &Ag[arow * 256 + (kk) + acq]);                                   \
        cpa16(sbase + (arow * GA_PITCH + acq + 8) * 2,                         \
              &Ag[arow * 256 + (kk) + acq + 8]);                               \
        cpa16(sbase + GB_OFF + (brow * GB_PITCH + bcq) * 2,                    \
              &g_wq_h[((kk) + brow) * 768 + n0 + bcq]);                        \
        cpa16(sbase + GB_OFF + (brow * GB_PITCH + bcq + 8) * 2,                \
              &g_wq_h[((kk) + brow) * 768 + n0 + bcq + 8]);                    \
    } while (0)

    QKV_COPY(0, 0);
    CPA_COMMIT();

    float acc[2][8][4] = {};
    int cur = 0;
    for (int ki = 0; ki < 8; ki++) {
        int nxt = cur + 1; if (nxt == 3) nxt = 0;
        if (ki < 7) {
            QKV_COPY(nxt, (ki + 1) * 32);
            CPA_COMMIT();
            CPA_WAIT1();
        } else {
            CPA_WAIT0();
        }
        __syncthreads();
        const uint32_t abase = sb + cur * GST + a_off;
        const uint32_t bbase = sb + cur * GST + b_off;
#pragma unroll
        for (int ks = 0; ks < 2; ks++) {
            uint32_t a0[4], a1[4];
            ldsm4(a0, abase + ks * 32);
            ldsm4(a1, abase + 16 * GA_PITCH * 2 + ks * 32);
#pragma unroll
            for (int ntp = 0; ntp < 4; ntp++) {
                uint32_t vb[4];
                ldsm4t(vb, bbase + ks * 16 * GB_PITCH * 2 + ntp * 32);
                mma16(acc[0][2 * ntp],     a0, vb[0], vb[1]);
                mma16(acc[0][2 * ntp + 1], a0, vb[2], vb[3]);
                mma16(acc[1][2 * ntp],     a1, vb[0], vb[1]);
                mma16(acc[1][2 * ntp + 1], a1, vb[2], vb[3]);
            }
        }
        cur = nxt;
    }
#pragma unroll
    for (int mt = 0; mt < 2; mt++)
#pragma unroll
        for (int nt = 0; nt < 8; nt++) {
            int row = m0 + wr * 32 + mt * 16 + g;
            int col = n0 + wc * 64 + nt * 8 + 2 * tg;
            *(uint32_t*)&g_qkv_h[(size_t)row * 768 + col] =
                f2h2(acc[mt][nt][0], acc[mt][nt][1]);
            *(uint32_t*)&g_qkv_h[(size_t)(row + 8) * 768 + col] =
                f2h2(acc[mt][nt][2], acc[mt][nt][3]);
        }
}

// ---- Proj GEMM: (16384 x 256) @ (256 x 256) + b -> out NCHW (transposed) ----
__global__ __launch_bounds__(256) void gemm_proj_h(const float* __restrict__ bias,
                                                   float* __restrict__ out) {
    extern __shared__ __align__(16) char smem[];
    const uint32_t sb = smem_u32(smem);
    const int t = threadIdx.x, w = t >> 5, lane = t & 31;
    const int sub = lane >> 3, g = lane >> 2, tg = lane & 3;
    const int wr = w >> 1, wc = w & 1;
    const int m0 = blockIdx.y * 128, n0 = blockIdx.x * 128;

    const uint32_t a_off =
        ((wr * 32 + (sub & 1) * 8 + (lane & 7)) * GA_PITCH + (sub >> 1) * 8) * 2;
    const uint32_t b_off = GB_OFF +
        (((sub & 1) * 8 + (lane & 7)) * GB_PITCH + wc * 64 + (sub >> 1) * 8) * 2;

    const __half* Ag = g_o_h + (size_t)m0 * 256;
    const int arow = t >> 1, acq = (t & 1) * 16;
    const int brow = t >> 3, bcq = (t & 7) * 16;

#define PJ_COPY(stg, kk)                                                       \
    do {                                                                       \
        uint32_t sbase = sb + (stg) * GST;                                     \
        cpa16(sbase + (arow * GA_PITCH + acq) * 2,                             \
              &Ag[arow * 256 + (kk) + acq]);                                   \
        cpa16(sbase + (arow * GA_PITCH + acq + 8) * 2,                         \
              &Ag[arow * 256 + (kk) + acq + 8]);                               \
        cpa16(sbase + GB_OFF + (brow * GB_PITCH + bcq) * 2,                    \
              &g_wp_h[((kk) + brow) * 256 + n0 + bcq]);                        \
        cpa16(sbase + GB_OFF + (brow * GB_PITCH + bcq + 8) * 2,                \
              &g_wp_h[((kk) + brow) * 256 + n0 + bcq + 8]);                    \
    } while (0)

    PJ_COPY(0, 0);
    CPA_COMMIT();

    float acc[2][8][4] = {};
    int cur = 0;
    for (int ki = 0; ki < 8; ki++) {
        int nxt = cur + 1; if (nxt == 3) nxt = 0;
        if (ki < 7) {
            PJ_COPY(nxt, (ki + 1) * 32);
            CPA_COMMIT();
            CPA_WAIT1();
        } else {
            CPA_WAIT0();
        }
        __syncthreads();
        const uint32_t abase = sb + cur * GST + a_off;
        const uint32_t bbase = sb + cur * GST + b_off;
#pragma unroll
        for (int ks = 0; ks < 2; ks++) {
            uint32_t a0[4], a1[4];
            ldsm4(a0, abase + ks * 32);
            ldsm4(a1, abase + 16 * GA_PITCH * 2 + ks * 32);
#pragma unroll
            for (int ntp = 0; ntp < 4; ntp++) {
                uint32_t vb[4];
                ldsm4t(vb, bbase + ks * 16 * GB_PITCH * 2 + ntp * 32);
                mma16(acc[0][2 * ntp],     a0, vb[0], vb[1]);
                mma16(acc[0][2 * ntp + 1], a0, vb[2], vb[3]);
                mma16(acc[1][2 * ntp],     a1, vb[0], vb[1]);
                mma16(acc[1][2 * ntp + 1], a1, vb[2], vb[3]);
            }
        }
        cur = nxt;
    }
    __syncthreads();

    // stage [c][m+pad] fp32 for coalesced transposed store
    float* st = (float*)smem;
#pragma unroll
    for (int mt = 0; mt < 2; mt++)
#pragma unroll
        for (int nt = 0; nt < 8; nt++) {
            int rl = wr * 32 + mt * 16 + g;
            int cl = wc * 64 + nt * 8 + 2 * tg;
            st[cl * 132 + rl]           = acc[mt][nt][0];
            st[(cl + 1) * 132 + rl]     = acc[mt][nt][1];
            st[cl * 132 + rl + 8]       = acc[mt][nt][2];
            st[(cl + 1) * 132 + rl + 8] = acc[mt][nt][3];
        }
    __syncthreads();

    const int ml = t & 31, wi = t >> 5;
    const int nimg = m0 >> 12, pbase = m0 & 4095;
#pragma unroll
    for (int i = 0; i < 16; i++) {
        int cl = wi + 8 * i;
        float bb = bias[n0 + cl];
        float* orow = out + ((size_t)(nimg * C + n0 + cl)) * HW + pbase;
#pragma unroll
        for (int ch = 0; ch < 4; ch++)
            orow[ml + 32 * ch] = st[cl * 132 + ml + 32 * ch] + bb;
    }
}

// ===========================================================================
// fp16 flash attention, 3-stage cp.async K/V pipeline, 1 barrier per kv-tile.
// Stage = K(64x72 half) + V(64x72 half) = 18432 B. P tile after stage 2.
// ===========================================================================
#define KV_STG   18432
#define PSB      (3 * KV_STG)          // 55296
#define SMEM_ATTN_B (PSB + 18432)      // 73728

__global__ __launch_bounds__(128) void attn_mma() {
    extern __shared__ char smraw[];
    const uint32_t sb = smem_u32(smraw);

    const int t    = threadIdx.x;
    const int w    = t >> 5;
    const int lane = t & 31;
    const int g    = lane >> 2;
    const int tg   = lane & 3;
    const int rb   = w * 32;

    const int qt = blockIdx.x;
    const int nh = blockIdx.y;
    const int n  = nh >> 2, h = nh & 3;
    const __half* qkvh = g_qkv_h + (size_t)n * HW * THREE_C;

    const int rowl = t >> 3;          // copy row lane 0..15
    const int c8   = (t & 7) * 8;     // copy column (8 halfs = 16 B)

    const uint32_t sub = lane >> 3;
    const uint32_t kf_off = ((((sub >> 1) * 8) + (lane & 7)) * 72 + (sub & 1) * 8) * 2;
    const uint32_t vf_off = 9216 +
        ((((sub & 1) * 8) + (lane & 7)) * 72 + (sub >> 1) * 8) * 2;
    const uint32_t pfb = sb + PSB +
        (((rb + (sub & 1) * 8) + (lane & 7)) * 72 + (sub >> 1) * 8) * 2;

#define ATTN_COPY(stg, kt_)                                                    \
    do {                                                                       \
        uint32_t sbase = sb + (stg) * KV_STG;                                  \
        _Pragma("unroll")                                                      \
        for (int i_ = 0; i_ < 4; i_++) {                                       \
            int row_ = rowl + 16 * i_;                                         \
            int rg_  = (kt_) * 64 + row_;                                      \
            int p_   = h * 1024 + (rg_ >> 2);                                  \
            int s_   = rg_ & 3;                                                \
            const __half* base_ = qkvh + (size_t)p_ * 768 + s_ * 192;          \
            cpa16(sbase + (row_ * 72 + c8) * 2, base_ + 64 + c8);              \
            cpa16(sbase + 9216 + (row_ * 72 + c8) * 2, base_ + 128 + c8);      \
        }                                                                      \
    } while (0)

    // Q A-frags in registers (direct half2 loads)
    uint32_t aq[2][4][4];
#pragma unroll
    for (int mt = 0; mt < 2; mt++)
#pragma unroll
        for (int rr = 0; rr < 2; rr++) {
            int r  = qt * 128 + rb + mt * 16 + rr * 8 + g;
            int p  = h * 1024 + (r >> 2);
            int s  = r & 3;
            const __half* qrow = qkvh + (size_t)p * 768 + s * 192;
#pragma unroll
            for (int ks = 0; ks < 4; ks++) {
                aq[mt][ks][rr]     = *(const uint32_t*)&qrow[ks * 16 + 2 * tg];
                aq[mt][ks][rr + 2] = *(const uint32_t*)&qrow[ks * 16 + 8 + 2 * tg];
            }
        }

    ATTN_COPY(0, 0);
    CPA_COMMIT();

    float co[2][8][4] = {};
    float lsum[2][2]  = {};

    int cur = 0;
    for (int kt = 0; kt < 64; kt++) {
        int nxt = cur + 1; if (nxt == 3) nxt = 0;
        if (kt < 63) {
            ATTN_COPY(nxt, kt + 1);
            CPA_COMMIT();
            CPA_WAIT1();
        } else {
            CPA_WAIT0();
        }
        __syncthreads();

        const uint32_t kfb = sb + cur * KV_STG + kf_off;
        const uint32_t vfb = sb + cur * KV_STG + vf_off;

        float sc[2][8][4] = {};
#pragma unroll
        for (int ks = 0; ks < 4; ks++) {
#pragma unroll
            for (int ntp = 0; ntp < 4; ntp++) {
                uint32_t kb[4];
                ldsm4(kb, kfb + ntp * 2304 + ks * 32);
                mma16(sc[0][2 * ntp],     aq[0][ks], kb[0], kb[1]);
                mma16(sc[0][2 * ntp + 1], aq[0][ks], kb[2], kb[3]);
                mma16(sc[1][2 * ntp],     aq[1][ks], kb[0], kb[1]);
                mma16(sc[1][2 * ntp + 1], aq[1][ks], kb[2], kb[3]);
            }
        }

#pragma unroll
        for (int mt = 0; mt < 2; mt++) {
            int r0 = rb + mt * 16 + g;
#pragma unroll
            for (int nt = 0; nt < 8; nt++) {
                float p0 = __expf(sc[mt][nt][0] * 0.125f);
                float p1 = __expf(sc[mt][nt][1] * 0.125f);
                float p2 = __expf(sc[mt][nt][2] * 0.125f);
                float p3 = __expf(sc[mt][nt][3] * 0.125f);
                lsum[mt][0] += p0 + p1;
                lsum[mt][1] += p2 + p3;
                *(uint32_t*)(smraw + PSB + (r0 * 72 + nt * 8 + 2 * tg) * 2) =
                    f2h2(p0, p1);
                *(uint32_t*)(smraw + PSB + ((r0 + 8) * 72 + nt * 8 + 2 * tg) * 2) =
                    f2h2(p2, p3);
            }
        }
        __syncwarp();

#pragma unroll
        for (int ks = 0; ks < 4; ks++) {
            uint32_t pa0[4], pa1[4];
            ldsm4(pa0, pfb + ks * 32);
            ldsm4(pa1, pfb + 2304 + ks * 32);
#pragma unroll
            for (int ntp = 0; ntp < 4; ntp++) {
                uint32_t vb[4];
                ldsm4t(vb, vfb + ks * 2304 + ntp * 32);
                mma16(co[0][2 * ntp],     pa0, vb[0], vb[1]);
                mma16(co[0][2 * ntp + 1], pa0, vb[2], vb[3]);
                mma16(co[1][2 * ntp],     pa1, vb[0], vb[1]);
                mma16(co[1][2 * ntp + 1], pa1, vb[2], vb[3]);
            }
        }
        cur = nxt;
    }

    // finalize: quad row-sum reduce, normalize, stage as half, store
    float inv[2][2];
#pragma unroll
    for (int mt = 0; mt < 2; mt++)
#pragma unroll
        for (int hh = 0; hh < 2; hh++) {
            float l = lsum[mt][hh];
            l += __shfl_xor_sync(0xffffffffu, l, 1);
            l += __shfl_xor_sync(0xffffffffu, l, 2);
            inv[mt][hh] = 1.f / l;
        }
    __syncthreads();   // done with K/V smem; reuse as half staging [128][80]
#pragma unroll
    for (int mt = 0; mt < 2; mt++) {
        int r0 = rb + mt * 16 + g;
#pragma unroll
        for (int nt = 0; nt < 8; nt++) {
            *(uint32_t*)(smraw + (r0 * 80 + nt * 8 + 2 * tg) * 2) =
                f2h2(co[mt][nt][0] * inv[mt][0], co[mt][nt][1] * inv[mt][0]);
            *(uint32_t*)(smraw + ((r0 + 8) * 80 + nt * 8 + 2 * tg) * 2) =
                f2h2(co[mt][nt][2] * inv[mt][1], co[mt][nt][3] * inv[mt][1]);
        }
    }
    __syncthreads();
    {
        int rg = qt * 128 + t;
        int p  = h * 1024 + (rg >> 2);
        int s  = rg & 3;
        __half* dst = g_o_h + ((size_t)n * HW + p) * C + s * 64;
#pragma unroll
        for (int j = 0; j < 8; j++)
            *(uint4*)&dst[8 * j] = *(uint4*)(smraw + (t * 80 + 8 * j) * 2);
    }
}

// ---------------------------------------------------------------------------
// BatchNorm statistics -> per-channel scale/shift
// ---------------------------------------------------------------------------
__global__ void bn_stats(const float* __restrict__ x,
                         const float* __restrict__ gamma,
                         const float* __restrict__ beta) {
    int c = blockIdx.x;
    int t = threadIdx.x;
    float s = 0.f, s2 = 0.f;
    for (int n = 0; n < N_IMG; n++) {
        const float* p = x + ((size_t)n * C + c) * HW;
        for (int i = t; i < HW; i += 256) {
            float v = p[i];
            s += v;
            s2 += v * v;
        }
    }
    __shared__ float sh0[256], sh1[256];
    sh0[t] = s; sh1[t] = s2;
    __syncthreads();
    for (int o = 128; o > 0; o >>= 1) {
        if (t < o) { sh0[t] += sh0[t + o]; sh1[t] += sh1[t + o]; }
        __syncthreads();
    }
    if (t == 0) {
        const float inv = 1.f / (float)(N_IMG * HW);
        float mean = sh0[0] * inv;
        float var  = sh1[0] * inv - mean * mean;
        float rstd = rsqrtf(var + 1e-5f);
        float sc   = gamma[c] * rstd;
        g_scale[c] = sc;
        g_shift[c] = beta[c] - mean * sc;
    }
}

// ---------------------------------------------------------------------------
// Normalize + transpose (n,c,hw) -> (n,hw,c) as half
// ---------------------------------------------------------------------------
__global__ void norm_transpose(const float* __restrict__ x) {
    __shared__ float tile[32][33];
    int n  = blockIdx.z;
    int c0 = blockIdx.y * 32;
    int p0 = blockIdx.x * 32;
    int tx = threadIdx.x, ty = threadIdx.y;  // 32 x 8
#pragma unroll
    for (int j = 0; j < 4; j++) {
        int c = c0 + ty + j * 8;
        tile[ty + j * 8][tx] =
            x[((size_t)n * C + c) * HW + p0 + tx] * g_scale[c] + g_shift[c];
    }
    __syncthreads();
#pragma unroll
    for (int j = 0; j < 4; j++) {
        int p = p0 + ty + j * 8;
        g_seq_h[((size_t)n * HW + p) * C + c0 + tx] = __float2half_rn(tile[tx][ty + j * 8]);
    }
}

// ---------------------------------------------------------------------------
// Weight pre-conversion (once per launch; deterministic)
// ---------------------------------------------------------------------------
__global__ void convert_w(const float* __restrict__ qkv_w,
                          const float* __restrict__ proj_w) {
    int i = blockIdx.x * 256 + threadIdx.x;
    if (i < C * THREE_C) g_wq_h[i] = __float2half_rn(qkv_w[i]);
    int j = i - C * THREE_C;
    if (j >= 0 && j < C * C) g_wp_h[j] = __float2half_rn(proj_w[j]);
}

// ---------------------------------------------------------------------------
extern "C" void kernel_launch(void* const* d_in, const int* in_sizes, int n_in,
                              void* d_out, int out_size) {
    const float* x      = (const float*)d_in[0];
    const float* gamma  = (const float*)d_in[1];
    const float* beta   = (const float*)d_in[2];
    const float* qkv_w  = (const float*)d_in[3];
    const float* proj_w = (const float*)d_in[4];
    const float* proj_b = (const float*)d_in[5];
    float* out = (float*)d_out;

    cudaFuncSetAttribute(gemm_qkv_h,
                         cudaFuncAttributeMaxDynamicSharedMemorySize, QK_SMEM);
    cudaFuncSetAttribute(gemm_proj_h,
                         cudaFuncAttributeMaxDynamicSharedMemorySize, PJ_SMEM);
    cudaFuncSetAttribute(attn_mma,
                         cudaFuncAttributeMaxDynamicSharedMemorySize, SMEM_ATTN_B);

    bn_stats<<<256, 256>>>(x, gamma, beta);
    norm_transpose<<<dim3(128, 8, 4), dim3(32, 8)>>>(x);
    convert_w<<<(C * THREE_C + C * C) / 256, 256>>>(qkv_w, proj_w);
    gemm_qkv_h<<<dim3(6, 128), 256, QK_SMEM>>>();
    attn_mma<<<dim3(32, 16), 128, SMEM_ATTN_B>>>();
    gemm_proj_h<<<dim3(2, 128), 256, PJ_SMEM>>>(proj_b, out);
}

// round 8
// speedup vs baseline: 3.0933x; 1.0211x over previous
#include <cuda_runtime.h>
#include <cuda_fp16.h>
#include <math.h>
#include <stdint.h>

#define N_IMG   4
#define C       256
#define HW      4096
#define THREE_C 768

// Scratch (device globals: allocation-free rule)
__device__ float g_scale[C];
__device__ float g_shift[C];
__device__ __align__(16) __half g_seq_h[N_IMG * HW * C];
__device__ __align__(16) __half g_qkv_h[N_IMG * HW * THREE_C];
__device__ __align__(16) __half g_o_h[N_IMG * HW * C];
__device__ __align__(16) __half g_wq_h[C * THREE_C];
__device__ __align__(16) __half g_wp_h[C * C];

__device__ __forceinline__ uint32_t smem_u32(const void* p) {
    uint32_t a;
    asm("{ .reg .u64 t; cvta.to.shared.u64 t, %1; cvt.u32.u64 %0, t; }"
        : "=r"(a) : "l"(p));
    return a;
}
__device__ __forceinline__ uint32_t f2h2(float lo, float hi) {
    uint32_t u;
    asm("cvt.rn.f16x2.f32 %0, %1, %2;" : "=r"(u) : "f"(hi), "f"(lo));
    return u;
}
__device__ __forceinline__ void mma16(float* d, const uint32_t* a,
                                      uint32_t b0, uint32_t b1) {
    asm volatile(
        "mma.sync.aligned.m16n8k16.row.col.f32.f16.f16.f32 "
        "{%0,%1,%2,%3}, {%4,%5,%6,%7}, {%8,%9}, {%0,%1,%2,%3};"
        : "+f"(d[0]), "+f"(d[1]), "+f"(d[2]), "+f"(d[3])
        : "r"(a[0]), "r"(a[1]), "r"(a[2]), "r"(a[3]), "r"(b0), "r"(b1));
}
__device__ __forceinline__ void ldsm4(uint32_t* r, uint32_t a) {
    asm volatile("ldmatrix.sync.aligned.m8n8.x4.shared.b16 {%0,%1,%2,%3}, [%4];"
                 : "=r"(r[0]), "=r"(r[1]), "=r"(r[2]), "=r"(r[3]) : "r"(a));
}
__device__ __forceinline__ void ldsm4t(uint32_t* r, uint32_t a) {
    asm volatile("ldmatrix.sync.aligned.m8n8.x4.trans.shared.b16 {%0,%1,%2,%3}, [%4];"
                 : "=r"(r[0]), "=r"(r[1]), "=r"(r[2]), "=r"(r[3]) : "r"(a));
}
__device__ __forceinline__ void cpa16(uint32_t dst, const void* src) {
    asm volatile("cp.async.ca.shared.global [%0], [%1], 16;"
                 :: "r"(dst), "l"(src));
}
#define CPA_COMMIT() asm volatile("cp.async.commit_group;" ::: "memory")
#define CPA_WAIT1()  asm volatile("cp.async.wait_group 1;" ::: "memory")
#define CPA_WAIT0()  asm volatile("cp.async.wait_group 0;" ::: "memory")

// ===========================================================================
// fp16 GEMM core: BM=128, BN=128, BK=32, 256 threads (8 warps, 4m x 2n),
// 3-stage cp.async pipeline, ONE barrier per k-iteration.
// ===========================================================================
#define GA_PITCH 40
#define GB_PITCH 136
#define GB_OFF   (128 * GA_PITCH * 2)                // 10240 B (A stage)
#define GST      (GB_OFF + 32 * GB_PITCH * 2)        // 18944 B per stage
#define QK_SMEM  (3 * GST)                           // 56832 B
#define PJ_SMEM  (128 * 132 * 4)                     // 67584 B (proj staging)

// ---- QKV GEMM: (16384 x 256) @ (256 x 768) -> g_qkv_h ----
__global__ __launch_bounds__(256) void gemm_qkv_h() {
    extern __shared__ __align__(16) char smem[];
    const uint32_t sb = smem_u32(smem);
    const int t = threadIdx.x, w = t >> 5, lane = t & 31;
    const int sub = lane >> 3, g = lane >> 2, tg = lane & 3;
    const int wr = w >> 1, wc = w & 1;
    const int m0 = blockIdx.y * 128, n0 = blockIdx.x * 128;

    const uint32_t a_off =
        ((wr * 32 + (sub & 1) * 8 + (lane & 7)) * GA_PITCH + (sub >> 1) * 8) * 2;
    const uint32_t b_off = GB_OFF +
        (((sub & 1) * 8 + (lane & 7)) * GB_PITCH + wc * 64 + (sub >> 1) * 8) * 2;

    const __half* Ag = g_seq_h + (size_t)m0 * 256;
    const int arow = t >> 1, acq = (t & 1) * 16;
    const int brow = t >> 3, bcq = (t & 7) * 16;

#define QKV_COPY(stg, kk)                                                      \
    do {                                                                       \
        uint32_t sbase = sb + (stg) * GST;                                     \
        cpa16(sbase + (arow * GA_PITCH + acq) * 2,                             \
              &Ag[arow * 256 + (kk) + acq]);                                   \
        cpa16(sbase + (arow * GA_PITCH + acq + 8) * 2,                         \
              &Ag[arow * 256 + (kk) + acq + 8]);                               \
        cpa16(sbase + GB_OFF + (brow * GB_PITCH + bcq) * 2,                    \
              &g_wq_h[((kk) + brow) * 768 + n0 + bcq]);                        \
        cpa16(sbase + GB_OFF + (brow * GB_PITCH + bcq + 8) * 2,                \
              &g_wq_h[((kk) + brow) * 768 + n0 + bcq + 8]);                    \
    } while (0)

    QKV_COPY(0, 0);
    CPA_COMMIT();

    float acc[2][8][4] = {};
    int cur = 0;
    for (int ki = 0; ki < 8; ki++) {
        int nxt = cur + 1; if (nxt == 3) nxt = 0;
        if (ki < 7) {
            QKV_COPY(nxt, (ki + 1) * 32);
            CPA_COMMIT();
            CPA_WAIT1();
        } else {
            CPA_WAIT0();
        }
        __syncthreads();
        const uint32_t abase = sb + cur * GST + a_off;
        const uint32_t bbase = sb + cur * GST + b_off;
#pragma unroll
        for (int ks = 0; ks < 2; ks++) {
            uint32_t a0[4], a1[4];
            ldsm4(a0, abase + ks * 32);
            ldsm4(a1, abase + 16 * GA_PITCH * 2 + ks * 32);
#pragma unroll
            for (int ntp = 0; ntp < 4; ntp++) {
                uint32_t vb[4];
                ldsm4t(vb, bbase + ks * 16 * GB_PITCH * 2 + ntp * 32);
                mma16(acc[0][2 * ntp],     a0, vb[0], vb[1]);
                mma16(acc[0][2 * ntp + 1], a0, vb[2], vb[3]);
                mma16(acc[1][2 * ntp],     a1, vb[0], vb[1]);
                mma16(acc[1][2 * ntp + 1], a1, vb[2], vb[3]);
            }
        }
        cur = nxt;
    }
#pragma unroll
    for (int mt = 0; mt < 2; mt++)
#pragma unroll
        for (int nt = 0; nt < 8; nt++) {
            int row = m0 + wr * 32 + mt * 16 + g;
            int col = n0 + wc * 64 + nt * 8 + 2 * tg;
            *(uint32_t*)&g_qkv_h[(size_t)row * 768 + col] =
                f2h2(acc[mt][nt][0], acc[mt][nt][1]);
            *(uint32_t*)&g_qkv_h[(size_t)(row + 8) * 768 + col] =
                f2h2(acc[mt][nt][2], acc[mt][nt][3]);
        }
}

// ---- Proj GEMM: (16384 x 256) @ (256 x 256) + b -> out NCHW (transposed) ----
__global__ __launch_bounds__(256) void gemm_proj_h(const float* __restrict__ bias,
                                                   float* __restrict__ out) {
    extern __shared__ __align__(16) char smem[];
    const uint32_t sb = smem_u32(smem);
    const int t = threadIdx.x, w = t >> 5, lane = t & 31;
    const int sub = lane >> 3, g = lane >> 2, tg = lane & 3;
    const int wr = w >> 1, wc = w & 1;
    const int m0 = blockIdx.y * 128, n0 = blockIdx.x * 128;

    const uint32_t a_off =
        ((wr * 32 + (sub & 1) * 8 + (lane & 7)) * GA_PITCH + (sub >> 1) * 8) * 2;
    const uint32_t b_off = GB_OFF +
        (((sub & 1) * 8 + (lane & 7)) * GB_PITCH + wc * 64 + (sub >> 1) * 8) * 2;

    const __half* Ag = g_o_h + (size_t)m0 * 256;
    const int arow = t >> 1, acq = (t & 1) * 16;
    const int brow = t >> 3, bcq = (t & 7) * 16;

#define PJ_COPY(stg, kk)                                                       \
    do {                                                                       \
        uint32_t sbase = sb + (stg) * GST;                                     \
        cpa16(sbase + (arow * GA_PITCH + acq) * 2,                             \
              &Ag[arow * 256 + (kk) + acq]);                                   \
        cpa16(sbase + (arow * GA_PITCH + acq + 8) * 2,                         \
              &Ag[arow * 256 + (kk) + acq + 8]);                               \
        cpa16(sbase + GB_OFF + (brow * GB_PITCH + bcq) * 2,                    \
              &g_wp_h[((kk) + brow) * 256 + n0 + bcq]);                        \
        cpa16(sbase + GB_OFF + (brow * GB_PITCH + bcq + 8) * 2,                \
              &g_wp_h[((kk) + brow) * 256 + n0 + bcq + 8]);                    \
    } while (0)

    PJ_COPY(0, 0);
    CPA_COMMIT();

    float acc[2][8][4] = {};
    int cur = 0;
    for (int ki = 0; ki < 8; ki++) {
        int nxt = cur + 1; if (nxt == 3) nxt = 0;
        if (ki < 7) {
            PJ_COPY(nxt, (ki + 1) * 32);
            CPA_COMMIT();
            CPA_WAIT1();
        } else {
            CPA_WAIT0();
        }
        __syncthreads();
        const uint32_t abase = sb + cur * GST + a_off;
        const uint32_t bbase = sb + cur * GST + b_off;
#pragma unroll
        for (int ks = 0; ks < 2; ks++) {
            uint32_t a0[4], a1[4];
            ldsm4(a0, abase + ks * 32);
            ldsm4(a1, abase + 16 * GA_PITCH * 2 + ks * 32);
#pragma unroll
            for (int ntp = 0; ntp < 4; ntp++) {
                uint32_t vb[4];
                ldsm4t(vb, bbase + ks * 16 * GB_PITCH * 2 + ntp * 32);
                mma16(acc[0][2 * ntp],     a0, vb[0], vb[1]);
                mma16(acc[0][2 * ntp + 1], a0, vb[2], vb[3]);
                mma16(acc[1][2 * ntp],     a1, vb[0], vb[1]);
                mma16(acc[1][2 * ntp + 1], a1, vb[2], vb[3]);
            }
        }
        cur = nxt;
    }
    __syncthreads();

    // stage [c][m+pad] fp32 for coalesced transposed store
    float* st = (float*)smem;
#pragma unroll
    for (int mt = 0; mt < 2; mt++)
#pragma unroll
        for (int nt = 0; nt < 8; nt++) {
            int rl = wr * 32 + mt * 16 + g;
            int cl = wc * 64 + nt * 8 + 2 * tg;
            st[cl * 132 + rl]           = acc[mt][nt][0];
            st[(cl + 1) * 132 + rl]     = acc[mt][nt][1];
            st[cl * 132 + rl + 8]       = acc[mt][nt][2];
            st[(cl + 1) * 132 + rl + 8] = acc[mt][nt][3];
        }
    __syncthreads();

    const int ml = t & 31, wi = t >> 5;
    const int nimg = m0 >> 12, pbase = m0 & 4095;
#pragma unroll
    for (int i = 0; i < 16; i++) {
        int cl = wi + 8 * i;
        float bb = bias[n0 + cl];
        float* orow = out + ((size_t)(nimg * C + n0 + cl)) * HW + pbase;
#pragma unroll
        for (int ch = 0; ch < 4; ch++)
            orow[ml + 32 * ch] = st[cl * 132 + ml + 32 * ch] + bb;
    }
}

// ===========================================================================
// fp16 flash attention, 3-stage cp.async K/V pipeline, register-resident P
// (S C-fragments exp'd and repacked directly as PV A-fragments; no P smem).
// Stage = K(64x72 half) + V(64x72 half) = 18432 B.
// ===========================================================================
#define KV_STG   18432
#define SMEM_ATTN_B (3 * KV_STG)       // 55296 -> 3 CTAs/SM

__global__ __launch_bounds__(128, 3) void attn_mma() {
    extern __shared__ char smraw[];
    const uint32_t sb = smem_u32(smraw);

    const int t    = threadIdx.x;
    const int w    = t >> 5;
    const int lane = t & 31;
    const int g    = lane >> 2;
    const int tg   = lane & 3;
    const int rb   = w * 32;

    const int qt = blockIdx.x;
    const int nh = blockIdx.y;
    const int n  = nh >> 2, h = nh & 3;
    const __half* qkvh = g_qkv_h + (size_t)n * HW * THREE_C;

    const int rowl = t >> 3;          // copy row lane 0..15
    const int c8   = (t & 7) * 8;     // copy column (8 halfs = 16 B)

    const uint32_t sub = lane >> 3;
    const uint32_t kf_off = ((((sub >> 1) * 8) + (lane & 7)) * 72 + (sub & 1) * 8) * 2;
    const uint32_t vf_off = 9216 +
        ((((sub & 1) * 8) + (lane & 7)) * 72 + (sub >> 1) * 8) * 2;

#define ATTN_COPY(stg, kt_)                                                    \
    do {                                                                       \
        uint32_t sbase = sb + (stg) * KV_STG;                                  \
        _Pragma("unroll")                                                      \
        for (int i_ = 0; i_ < 4; i_++) {                                       \
            int row_ = rowl + 16 * i_;                                         \
            int rg_  = (kt_) * 64 + row_;                                      \
            int p_   = h * 1024 + (rg_ >> 2);                                  \
            int s_   = rg_ & 3;                                                \
            const __half* base_ = qkvh + (size_t)p_ * 768 + s_ * 192;          \
            cpa16(sbase + (row_ * 72 + c8) * 2, base_ + 64 + c8);              \
            cpa16(sbase + 9216 + (row_ * 72 + c8) * 2, base_ + 128 + c8);      \
        }                                                                      \
    } while (0)

    // Q A-frags in registers (direct half2 loads)
    uint32_t aq[2][4][4];
#pragma unroll
    for (int mt = 0; mt < 2; mt++)
#pragma unroll
        for (int rr = 0; rr < 2; rr++) {
            int r  = qt * 128 + rb + mt * 16 + rr * 8 + g;
            int p  = h * 1024 + (r >> 2);
            int s  = r & 3;
            const __half* qrow = qkvh + (size_t)p * 768 + s * 192;
#pragma unroll
            for (int ks = 0; ks < 4; ks++) {
                aq[mt][ks][rr]     = *(const uint32_t*)&qrow[ks * 16 + 2 * tg];
                aq[mt][ks][rr + 2] = *(const uint32_t*)&qrow[ks * 16 + 8 + 2 * tg];
            }
        }

    ATTN_COPY(0, 0);
    CPA_COMMIT();

    float co[2][8][4] = {};
    float lsum[2][2]  = {};

    int cur = 0;
    for (int kt = 0; kt < 64; kt++) {
        int nxt = cur + 1; if (nxt == 3) nxt = 0;
        if (kt < 63) {
            ATTN_COPY(nxt, kt + 1);
            CPA_COMMIT();
            CPA_WAIT1();
        } else {
            CPA_WAIT0();
        }
        __syncthreads();

        const uint32_t kfb = sb + cur * KV_STG + kf_off;
        const uint32_t vfb = sb + cur * KV_STG + vf_off;

        // ---- S = Q K^T per ntp (kv group of 16), exp + pack into PV A-frags
        uint32_t pa[2][4][4];
#pragma unroll
        for (int ntp = 0; ntp < 4; ntp++) {
            float s00[4] = {}, s01[4] = {}, s10[4] = {}, s11[4] = {};
#pragma unroll
            for (int ks = 0; ks < 4; ks++) {
                uint32_t kb[4];
                ldsm4(kb, kfb + ntp * 2304 + ks * 32);
                mma16(s00, aq[0][ks], kb[0], kb[1]);   // mt0, kv low 8
                mma16(s01, aq[0][ks], kb[2], kb[3]);   // mt0, kv high 8
                mma16(s10, aq[1][ks], kb[0], kb[1]);   // mt1, kv low 8
                mma16(s11, aq[1][ks], kb[2], kb[3]);   // mt1, kv high 8
            }
            {
                float a0 = __expf(s00[0] * 0.125f), a1 = __expf(s00[1] * 0.125f);
                float a2 = __expf(s00[2] * 0.125f), a3 = __expf(s00[3] * 0.125f);
                float b0 = __expf(s01[0] * 0.125f), b1 = __expf(s01[1] * 0.125f);
                float b2 = __expf(s01[2] * 0.125f), b3 = __expf(s01[3] * 0.125f);
                lsum[0][0] += (a0 + a1) + (b0 + b1);
                lsum[0][1] += (a2 + a3) + (b2 + b3);
                pa[0][ntp][0] = f2h2(a0, a1);
                pa[0][ntp][1] = f2h2(a2, a3);
                pa[0][ntp][2] = f2h2(b0, b1);
                pa[0][ntp][3] = f2h2(b2, b3);
            }
            {
                float a0 = __expf(s10[0] * 0.125f), a1 = __expf(s10[1] * 0.125f);
                float a2 = __expf(s10[2] * 0.125f), a3 = __expf(s10[3] * 0.125f);
                float b0 = __expf(s11[0] * 0.125f), b1 = __expf(s11[1] * 0.125f);
                float b2 = __expf(s11[2] * 0.125f), b3 = __expf(s11[3] * 0.125f);
                lsum[1][0] += (a0 + a1) + (b0 + b1);
                lsum[1][1] += (a2 + a3) + (b2 + b3);
                pa[1][ntp][0] = f2h2(a0, a1);
                pa[1][ntp][1] = f2h2(a2, a3);
                pa[1][ntp][2] = f2h2(b0, b1);
                pa[1][ntp][3] = f2h2(b2, b3);
            }
        }

        // ---- O += P V (P from registers) ----
#pragma unroll
        for (int ks = 0; ks < 4; ks++) {
#pragma unroll
            for (int ntp = 0; ntp < 4; ntp++) {
                uint32_t vb[4];
                ldsm4t(vb, vfb + ks * 2304 + ntp * 32);
                mma16(co[0][2 * ntp],     pa[0][ks], vb[0], vb[1]);
                mma16(co[0][2 * ntp + 1], pa[0][ks], vb[2], vb[3]);
                mma16(co[1][2 * ntp],     pa[1][ks], vb[0], vb[1]);
                mma16(co[1][2 * ntp + 1], pa[1][ks], vb[2], vb[3]);
            }
        }
        cur = nxt;
    }

    // finalize: quad row-sum reduce, normalize, stage as half, store
    float inv[2][2];
#pragma unroll
    for (int mt = 0; mt < 2; mt++)
#pragma unroll
        for (int hh = 0; hh < 2; hh++) {
            float l = lsum[mt][hh];
            l += __shfl_xor_sync(0xffffffffu, l, 1);
            l += __shfl_xor_sync(0xffffffffu, l, 2);
            inv[mt][hh] = 1.f / l;
        }
    __syncthreads();   // done with K/V smem; reuse as half staging [128][80]
#pragma unroll
    for (int mt = 0; mt < 2; mt++) {
        int r0 = rb + mt * 16 + g;
#pragma unroll
        for (int nt = 0; nt < 8; nt++) {
            *(uint32_t*)(smraw + (r0 * 80 + nt * 8 + 2 * tg) * 2) =
                f2h2(co[mt][nt][0] * inv[mt][0], co[mt][nt][1] * inv[mt][0]);
            *(uint32_t*)(smraw + ((r0 + 8) * 80 + nt * 8 + 2 * tg) * 2) =
                f2h2(co[mt][nt][2] * inv[mt][1], co[mt][nt][3] * inv[mt][1]);
        }
    }
    __syncthreads();
    {
        int rg = qt * 128 + t;
        int p  = h * 1024 + (rg >> 2);
        int s  = rg & 3;
        __half* dst = g_o_h + ((size_t)n * HW + p) * C + s * 64;
#pragma unroll
        for (int j = 0; j < 8; j++)
            *(uint4*)&dst[8 * j] = *(uint4*)(smraw + (t * 80 + 8 * j) * 2);
    }
}

// ---------------------------------------------------------------------------
// BatchNorm statistics -> per-channel scale/shift
// ---------------------------------------------------------------------------
__global__ void bn_stats(const float* __restrict__ x,
                         const float* __restrict__ gamma,
                         const float* __restrict__ beta) {
    int c = blockIdx.x;
    int t = threadIdx.x;
    float s = 0.f, s2 = 0.f;
    for (int n = 0; n < N_IMG; n++) {
        const float* p = x + ((size_t)n * C + c) * HW;
        for (int i = t; i < HW; i += 256) {
            float v = p[i];
            s += v;
            s2 += v * v;
        }
    }
    __shared__ float sh0[256], sh1[256];
    sh0[t] = s; sh1[t] = s2;
    __syncthreads();
    for (int o = 128; o > 0; o >>= 1) {
        if (t < o) { sh0[t] += sh0[t + o]; sh1[t] += sh1[t + o]; }
        __syncthreads();
    }
    if (t == 0) {
        const float inv = 1.f / (float)(N_IMG * HW);
        float mean = sh0[0] * inv;
        float var  = sh1[0] * inv - mean * mean;
        float rstd = rsqrtf(var + 1e-5f);
        float sc   = gamma[c] * rstd;
        g_scale[c] = sc;
        g_shift[c] = beta[c] - mean * sc;
    }
}

// ---------------------------------------------------------------------------
// Normalize + transpose (n,c,hw) -> (n,hw,c) as half
// ---------------------------------------------------------------------------
__global__ void norm_transpose(const float* __restrict__ x) {
    __shared__ float tile[32][33];
    int n  = blockIdx.z;
    int c0 = blockIdx.y * 32;
    int p0 = blockIdx.x * 32;
    int tx = threadIdx.x, ty = threadIdx.y;  // 32 x 8
#pragma unroll
    for (int j = 0; j < 4; j++) {
        int c = c0 + ty + j * 8;
        tile[ty + j * 8][tx] =
            x[((size_t)n * C + c) * HW + p0 + tx] * g_scale[c] + g_shift[c];
    }
    __syncthreads();
#pragma unroll
    for (int j = 0; j < 4; j++) {
        int p = p0 + ty + j * 8;
        g_seq_h[((size_t)n * HW + p) * C + c0 + tx] = __float2half_rn(tile[tx][ty + j * 8]);
    }
}

// ---------------------------------------------------------------------------
// Weight pre-conversion (once per launch; deterministic)
// ---------------------------------------------------------------------------
__global__ void convert_w(const float* __restrict__ qkv_w,
                          const float* __restrict__ proj_w) {
    int i = blockIdx.x * 256 + threadIdx.x;
    if (i < C * THREE_C) g_wq_h[i] = __float2half_rn(qkv_w[i]);
    int j = i - C * THREE_C;
    if (j >= 0 && j < C * C) g_wp_h[j] = __float2half_rn(proj_w[j]);
}

// ---------------------------------------------------------------------------
extern "C" void kernel_launch(void* const* d_in, const int* in_sizes, int n_in,
                              void* d_out, int out_size) {
    const float* x      = (const float*)d_in[0];
    const float* gamma  = (const float*)d_in[1];
    const float* beta   = (const float*)d_in[2];
    const float* qkv_w  = (const float*)d_in[3];
    const float* proj_w = (const float*)d_in[4];
    const float* proj_b = (const float*)d_in[5];
    float* out = (float*)d_out;

    cudaFuncSetAttribute(gemm_qkv_h,
                         cudaFuncAttributeMaxDynamicSharedMemorySize, QK_SMEM);
    cudaFuncSetAttribute(gemm_proj_h,
                         cudaFuncAttributeMaxDynamicSharedMemorySize, PJ_SMEM);
    cudaFuncSetAttribute(attn_mma,
                         cudaFuncAttributeMaxDynamicSharedMemorySize, SMEM_ATTN_B);

    bn_stats<<<256, 256>>>(x, gamma, beta);
    norm_transpose<<<dim3(128, 8, 4), dim3(32, 8)>>>(x);
    convert_w<<<(C * THREE_C + C * C) / 256, 256>>>(qkv_w, proj_w);
    gemm_qkv_h<<<dim3(6, 128), 256, QK_SMEM>>>();
    attn_mma<<<dim3(32, 16), 128, SMEM_ATTN_B>>>();
    gemm_proj_h<<<dim3(2, 128), 256, PJ_SMEM>>>(proj_b, out);
}

// round 9
// speedup vs baseline: 3.2393x; 1.0472x over previous
#include <cuda_runtime.h>
#include <cuda_fp16.h>
#include <math.h>
#include <stdint.h>

#define N_IMG   4
#define C       256
#define HW      4096
#define THREE_C 768

// Scratch (device globals: allocation-free rule)
__device__ float g_scale[C];
__device__ float g_shift[C];
__device__ __align__(16) __half g_seq_h[N_IMG * HW * C];
__device__ __align__(16) __half g_qkv_h[N_IMG * HW * THREE_C];
__device__ __align__(16) __half g_o_h[N_IMG * HW * C];
__device__ __align__(16) __half g_wq_h[C * THREE_C];
__device__ __align__(16) __half g_wp_h[C * C];

__device__ __forceinline__ uint32_t smem_u32(const void* p) {
    uint32_t a;
    asm("{ .reg .u64 t; cvta.to.shared.u64 t, %1; cvt.u32.u64 %0, t; }"
        : "=r"(a) : "l"(p));
    return a;
}
__device__ __forceinline__ uint32_t f2h2(float lo, float hi) {
    uint32_t u;
    asm("cvt.rn.f16x2.f32 %0, %1, %2;" : "=r"(u) : "f"(hi), "f"(lo));
    return u;
}
__device__ __forceinline__ void mma16(float* d, const uint32_t* a,
                                      uint32_t b0, uint32_t b1) {
    asm volatile(
        "mma.sync.aligned.m16n8k16.row.col.f32.f16.f16.f32 "
        "{%0,%1,%2,%3}, {%4,%5,%6,%7}, {%8,%9}, {%0,%1,%2,%3};"
        : "+f"(d[0]), "+f"(d[1]), "+f"(d[2]), "+f"(d[3])
        : "r"(a[0]), "r"(a[1]), "r"(a[2]), "r"(a[3]), "r"(b0), "r"(b1));
}
__device__ __forceinline__ void ldsm4(uint32_t* r, uint32_t a) {
    asm volatile("ldmatrix.sync.aligned.m8n8.x4.shared.b16 {%0,%1,%2,%3}, [%4];"
                 : "=r"(r[0]), "=r"(r[1]), "=r"(r[2]), "=r"(r[3]) : "r"(a));
}
__device__ __forceinline__ void ldsm4t(uint32_t* r, uint32_t a) {
    asm volatile("ldmatrix.sync.aligned.m8n8.x4.trans.shared.b16 {%0,%1,%2,%3}, [%4];"
                 : "=r"(r[0]), "=r"(r[1]), "=r"(r[2]), "=r"(r[3]) : "r"(a));
}
__device__ __forceinline__ void cpa16(uint32_t dst, const void* src) {
    asm volatile("cp.async.ca.shared.global [%0], [%1], 16;"
                 :: "r"(dst), "l"(src));
}
#define CPA_COMMIT() asm volatile("cp.async.commit_group;" ::: "memory")
#define CPA_WAIT1()  asm volatile("cp.async.wait_group 1;" ::: "memory")
#define CPA_WAIT0()  asm volatile("cp.async.wait_group 0;" ::: "memory")

// ===========================================================================
// fp16 GEMM core: BM=128, BN=128, BK=32, 256 threads (8 warps, 4m x 2n),
// 3-stage cp.async pipeline, ONE barrier per k-iteration.
// ===========================================================================
#define GA_PITCH 40
#define GB_PITCH 136
#define GB_OFF   (128 * GA_PITCH * 2)                // 10240 B (A stage)
#define GST      (GB_OFF + 32 * GB_PITCH * 2)        // 18944 B per stage
#define QK_SMEM  (3 * GST)                           // 56832 B
#define PJ_SMEM  (128 * 132 * 4)                     // 67584 B (proj staging)

// ---- QKV GEMM: (16384 x 256) @ (256 x 768) -> g_qkv_h ----
__global__ __launch_bounds__(256) void gemm_qkv_h() {
    extern __shared__ __align__(16) char smem[];
    const uint32_t sb = smem_u32(smem);
    const int t = threadIdx.x, w = t >> 5, lane = t & 31;
    const int sub = lane >> 3, g = lane >> 2, tg = lane & 3;
    const int wr = w >> 1, wc = w & 1;
    const int m0 = blockIdx.y * 128, n0 = blockIdx.x * 128;

    const uint32_t a_off =
        ((wr * 32 + (sub & 1) * 8 + (lane & 7)) * GA_PITCH + (sub >> 1) * 8) * 2;
    const uint32_t b_off = GB_OFF +
        (((sub & 1) * 8 + (lane & 7)) * GB_PITCH + wc * 64 + (sub >> 1) * 8) * 2;

    const __half* Ag = g_seq_h + (size_t)m0 * 256;
    const int arow = t >> 1, acq = (t & 1) * 16;
    const int brow = t >> 3, bcq = (t & 7) * 16;

#define QKV_COPY(stg, kk)                                                      \
    do {                                                                       \
        uint32_t sbase = sb + (stg) * GST;                                     \
        cpa16(sbase + (arow * GA_PITCH + acq) * 2,                             \
              &Ag[arow * 256 + (kk) + acq]);                                   \
        cpa16(sbase + (arow * GA_PITCH + acq + 8) * 2,                         \
              &Ag[arow * 256 + (kk) + acq + 8]);                               \
        cpa16(sbase + GB_OFF + (brow * GB_PITCH + bcq) * 2,                    \
              &g_wq_h[((kk) + brow) * 768 + n0 + bcq]);                        \
        cpa16(sbase + GB_OFF + (brow * GB_PITCH + bcq + 8) * 2,                \
              &g_wq_h[((kk) + brow) * 768 + n0 + bcq + 8]);                    \
    } while (0)

    QKV_COPY(0, 0);
    CPA_COMMIT();

    float acc[2][8][4] = {};
    int cur = 0;
    for (int ki = 0; ki < 8; ki++) {
        int nxt = cur + 1; if (nxt == 3) nxt = 0;
        if (ki < 7) {
            QKV_COPY(nxt, (ki + 1) * 32);
            CPA_COMMIT();
            CPA_WAIT1();
        } else {
            CPA_WAIT0();
        }
        __syncthreads();
        const uint32_t abase = sb + cur * GST + a_off;
        const uint32_t bbase = sb + cur * GST + b_off;
#pragma unroll
        for (int ks = 0; ks < 2; ks++) {
            uint32_t a0[4], a1[4];
            ldsm4(a0, abase + ks * 32);
            ldsm4(a1, abase + 16 * GA_PITCH * 2 + ks * 32);
#pragma unroll
            for (int ntp = 0; ntp < 4; ntp++) {
                uint32_t vb[4];
                ldsm4t(vb, bbase + ks * 16 * GB_PITCH * 2 + ntp * 32);
                mma16(acc[0][2 * ntp],     a0, vb[0], vb[1]);
                mma16(acc[0][2 * ntp + 1], a0, vb[2], vb[3]);
                mma16(acc[1][2 * ntp],     a1, vb[0], vb[1]);
                mma16(acc[1][2 * ntp + 1], a1, vb[2], vb[3]);
            }
        }
        cur = nxt;
    }
#pragma unroll
    for (int mt = 0; mt < 2; mt++)
#pragma unroll
        for (int nt = 0; nt < 8; nt++) {
            int row = m0 + wr * 32 + mt * 16 + g;
            int col = n0 + wc * 64 + nt * 8 + 2 * tg;
            *(uint32_t*)&g_qkv_h[(size_t)row * 768 + col] =
                f2h2(acc[mt][nt][0], acc[mt][nt][1]);
            *(uint32_t*)&g_qkv_h[(size_t)(row + 8) * 768 + col] =
                f2h2(acc[mt][nt][2], acc[mt][nt][3]);
        }
}

// ---- Proj GEMM: (16384 x 256) @ (256 x 256) + b -> out NCHW (transposed) ----
__global__ __launch_bounds__(256) void gemm_proj_h(const float* __restrict__ bias,
                                                   float* __restrict__ out) {
    extern __shared__ __align__(16) char smem[];
    const uint32_t sb = smem_u32(smem);
    const int t = threadIdx.x, w = t >> 5, lane = t & 31;
    const int sub = lane >> 3, g = lane >> 2, tg = lane & 3;
    const int wr = w >> 1, wc = w & 1;
    const int m0 = blockIdx.y * 128, n0 = blockIdx.x * 128;

    const uint32_t a_off =
        ((wr * 32 + (sub & 1) * 8 + (lane & 7)) * GA_PITCH + (sub >> 1) * 8) * 2;
    const uint32_t b_off = GB_OFF +
        (((sub & 1) * 8 + (lane & 7)) * GB_PITCH + wc * 64 + (sub >> 1) * 8) * 2;

    const __half* Ag = g_o_h + (size_t)m0 * 256;
    const int arow = t >> 1, acq = (t & 1) * 16;
    const int brow = t >> 3, bcq = (t & 7) * 16;

#define PJ_COPY(stg, kk)                                                       \
    do {                                                                       \
        uint32_t sbase = sb + (stg) * GST;                                     \
        cpa16(sbase + (arow * GA_PITCH + acq) * 2,                             \
              &Ag[arow * 256 + (kk) + acq]);                                   \
        cpa16(sbase + (arow * GA_PITCH + acq + 8) * 2,                         \
              &Ag[arow * 256 + (kk) + acq + 8]);                               \
        cpa16(sbase + GB_OFF + (brow * GB_PITCH + bcq) * 2,                    \
              &g_wp_h[((kk) + brow) * 256 + n0 + bcq]);                        \
        cpa16(sbase + GB_OFF + (brow * GB_PITCH + bcq + 8) * 2,                \
              &g_wp_h[((kk) + brow) * 256 + n0 + bcq + 8]);                    \
    } while (0)

    PJ_COPY(0, 0);
    CPA_COMMIT();

    float acc[2][8][4] = {};
    int cur = 0;
    for (int ki = 0; ki < 8; ki++) {
        int nxt = cur + 1; if (nxt == 3) nxt = 0;
        if (ki < 7) {
            PJ_COPY(nxt, (ki + 1) * 32);
            CPA_COMMIT();
            CPA_WAIT1();
        } else {
            CPA_WAIT0();
        }
        __syncthreads();
        const uint32_t abase = sb + cur * GST + a_off;
        const uint32_t bbase = sb + cur * GST + b_off;
#pragma unroll
        for (int ks = 0; ks < 2; ks++) {
            uint32_t a0[4], a1[4];
            ldsm4(a0, abase + ks * 32);
            ldsm4(a1, abase + 16 * GA_PITCH * 2 + ks * 32);
#pragma unroll
            for (int ntp = 0; ntp < 4; ntp++) {
                uint32_t vb[4];
                ldsm4t(vb, bbase + ks * 16 * GB_PITCH * 2 + ntp * 32);
                mma16(acc[0][2 * ntp],     a0, vb[0], vb[1]);
                mma16(acc[0][2 * ntp + 1], a0, vb[2], vb[3]);
                mma16(acc[1][2 * ntp],     a1, vb[0], vb[1]);
                mma16(acc[1][2 * ntp + 1], a1, vb[2], vb[3]);
            }
        }
        cur = nxt;
    }
    __syncthreads();

    // stage [c][m+pad] fp32 for coalesced transposed store
    float* st = (float*)smem;
#pragma unroll
    for (int mt = 0; mt < 2; mt++)
#pragma unroll
        for (int nt = 0; nt < 8; nt++) {
            int rl = wr * 32 + mt * 16 + g;
            int cl = wc * 64 + nt * 8 + 2 * tg;
            st[cl * 132 + rl]           = acc[mt][nt][0];
            st[(cl + 1) * 132 + rl]     = acc[mt][nt][1];
            st[cl * 132 + rl + 8]       = acc[mt][nt][2];
            st[(cl + 1) * 132 + rl + 8] = acc[mt][nt][3];
        }
    __syncthreads();

    const int ml = t & 31, wi = t >> 5;
    const int nimg = m0 >> 12, pbase = m0 & 4095;
#pragma unroll
    for (int i = 0; i < 16; i++) {
        int cl = wi + 8 * i;
        float bb = bias[n0 + cl];
        float* orow = out + ((size_t)(nimg * C + n0 + cl)) * HW + pbase;
#pragma unroll
        for (int ch = 0; ch < 4; ch++)
            orow[ml + 32 * ch] = st[cl * 132 + ml + 32 * ch] + bb;
    }
}

// ===========================================================================
// fp16 flash attention, 3-stage cp.async K/V pipeline, register-resident P,
// fine-grained S/exp/PV software pipeline (tensor and MUFU pipes overlapped).
// Q pre-scaled by 1/8 (exact in fp16 -> bit-identical results).
// ===========================================================================
#define KV_STG   18432
#define SMEM_ATTN_B (3 * KV_STG)       // 55296 -> 3 CTAs/SM

__global__ __launch_bounds__(128, 3) void attn_mma() {
    extern __shared__ char smraw[];
    const uint32_t sb = smem_u32(smraw);

    const int t    = threadIdx.x;
    const int w    = t >> 5;
    const int lane = t & 31;
    const int g    = lane >> 2;
    const int tg   = lane & 3;
    const int rb   = w * 32;

    const int qt = blockIdx.x;
    const int nh = blockIdx.y;
    const int n  = nh >> 2, h = nh & 3;
    const __half* qkvh = g_qkv_h + (size_t)n * HW * THREE_C;

    const int rowl = t >> 3;          // copy row lane 0..15
    const int c8   = (t & 7) * 8;     // copy column (8 halfs = 16 B)

    const uint32_t sub = lane >> 3;
    const uint32_t kf_off = ((((sub >> 1) * 8) + (lane & 7)) * 72 + (sub & 1) * 8) * 2;
    const uint32_t vf_off = 9216 +
        ((((sub & 1) * 8) + (lane & 7)) * 72 + (sub >> 1) * 8) * 2;

#define ATTN_COPY(stg, kt_)                                                    \
    do {                                                                       \
        uint32_t sbase = sb + (stg) * KV_STG;                                  \
        _Pragma("unroll")                                                      \
        for (int i_ = 0; i_ < 4; i_++) {                                       \
            int row_ = rowl + 16 * i_;                                         \
            int rg_  = (kt_) * 64 + row_;                                      \
            int p_   = h * 1024 + (rg_ >> 2);                                  \
            int s_   = rg_ & 3;                                                \
            const __half* base_ = qkvh + (size_t)p_ * 768 + s_ * 192;          \
            cpa16(sbase + (row_ * 72 + c8) * 2, base_ + 64 + c8);              \
            cpa16(sbase + 9216 + (row_ * 72 + c8) * 2, base_ + 128 + c8);      \
        }                                                                      \
    } while (0)

    // Q A-frags in registers, pre-scaled by 1/8 (exact power of 2 in fp16)
    uint32_t aq[2][4][4];
    {
        const __half2 kEighth = __floats2half2_rn(0.125f, 0.125f);
#pragma unroll
        for (int mt = 0; mt < 2; mt++)
#pragma unroll
            for (int rr = 0; rr < 2; rr++) {
                int r  = qt * 128 + rb + mt * 16 + rr * 8 + g;
                int p  = h * 1024 + (r >> 2);
                int s  = r & 3;
                const __half* qrow = qkvh + (size_t)p * 768 + s * 192;
#pragma unroll
                for (int ks = 0; ks < 4; ks++) {
                    __half2 v0 = *(const __half2*)&qrow[ks * 16 + 2 * tg];
                    __half2 v1 = *(const __half2*)&qrow[ks * 16 + 8 + 2 * tg];
                    v0 = __hmul2(v0, kEighth);
                    v1 = __hmul2(v1, kEighth);
                    aq[mt][ks][rr]     = *(uint32_t*)&v0;
                    aq[mt][ks][rr + 2] = *(uint32_t*)&v1;
                }
            }
    }

    ATTN_COPY(0, 0);
    CPA_COMMIT();

    float co[2][8][4] = {};
    float lsum[2][2]  = {};

    int cur = 0;
    for (int kt = 0; kt < 64; kt++) {
        int nxt = cur + 1; if (nxt == 3) nxt = 0;
        if (kt < 63) {
            ATTN_COPY(nxt, kt + 1);
            CPA_COMMIT();
            CPA_WAIT1();
        } else {
            CPA_WAIT0();
        }
        __syncthreads();

        const uint32_t kfb = sb + cur * KV_STG + kf_off;
        const uint32_t vfb = sb + cur * KV_STG + vf_off;

        uint32_t pa[2][4][4];
        float s00[4], s01[4], s10[4], s11[4];

#define S_BLK(j)                                                               \
    do {                                                                       \
        _Pragma("unroll")                                                      \
        for (int i_ = 0; i_ < 4; i_++) {                                       \
            s00[i_] = 0.f; s01[i_] = 0.f; s10[i_] = 0.f; s11[i_] = 0.f;        \
        }                                                                      \
        _Pragma("unroll")                                                      \
        for (int ks_ = 0; ks_ < 4; ks_++) {                                    \
            uint32_t kb_[4];                                                   \
            ldsm4(kb_, kfb + (j) * 2304 + ks_ * 32);                           \
            mma16(s00, aq[0][ks_], kb_[0], kb_[1]);                            \
            mma16(s01, aq[0][ks_], kb_[2], kb_[3]);                            \
            mma16(s10, aq[1][ks_], kb_[0], kb_[1]);                            \
            mma16(s11, aq[1][ks_], kb_[2], kb_[3]);                            \
        }                                                                      \
    } while (0)

#define EXP_BLK(j)                                                             \
    do {                                                                       \
        float a0 = __expf(s00[0]), a1 = __expf(s00[1]);                        \
        float a2 = __expf(s00[2]), a3 = __expf(s00[3]);                        \
        float b0 = __expf(s01[0]), b1 = __expf(s01[1]);                        \
        float b2 = __expf(s01[2]), b3 = __expf(s01[3]);                        \
        lsum[0][0] += (a0 + a1) + (b0 + b1);                                   \
        lsum[0][1] += (a2 + a3) + (b2 + b3);                                   \
        pa[0][j][0] = f2h2(a0, a1);                                            \
        pa[0][j][1] = f2h2(a2, a3);                                            \
        pa[0][j][2] = f2h2(b0, b1);                                            \
        pa[0][j][3] = f2h2(b2, b3);                                            \
        float c0 = __expf(s10[0]), c1 = __expf(s10[1]);                        \
        float c2 = __expf(s10[2]), c3 = __expf(s10[3]);                        \
        float d0 = __expf(s11[0]), d1 = __expf(s11[1]);                        \
        float d2 = __expf(s11[2]), d3 = __expf(s11[3]);                        \
        lsum[1][0] += (c0 + c1) + (d0 + d1);                                   \
        lsum[1][1] += (c2 + c3) + (d2 + d3);                                   \
        pa[1][j][0] = f2h2(c0, c1);                                            \
        pa[1][j][1] = f2h2(c2, c3);                                            \
        pa[1][j][2] = f2h2(d0, d1);                                            \
        pa[1][j][3] = f2h2(d2, d3);                                            \
    } while (0)

#define PV_BLK(j)                                                              \
    do {                                                                       \
        _Pragma("unroll")                                                      \
        for (int ntp_ = 0; ntp_ < 4; ntp_++) {                                 \
            uint32_t vb_[4];                                                   \
            ldsm4t(vb_, vfb + (j) * 2304 + ntp_ * 32);                         \
            mma16(co[0][2 * ntp_],     pa[0][j], vb_[0], vb_[1]);              \
            mma16(co[0][2 * ntp_ + 1], pa[0][j], vb_[2], vb_[3]);              \
            mma16(co[1][2 * ntp_],     pa[1][j], vb_[0], vb_[1]);              \
            mma16(co[1][2 * ntp_ + 1], pa[1][j], vb_[2], vb_[3]);              \
        }                                                                      \
    } while (0)

        S_BLK(0); EXP_BLK(0);
        S_BLK(1); PV_BLK(0); EXP_BLK(1);
        S_BLK(2); PV_BLK(1); EXP_BLK(2);
        S_BLK(3); PV_BLK(2); EXP_BLK(3);
        PV_BLK(3);

        cur = nxt;
    }

    // finalize: quad row-sum reduce, normalize, stage as half, store
    float inv[2][2];
#pragma unroll
    for (int mt = 0; mt < 2; mt++)
#pragma unroll
        for (int hh = 0; hh < 2; hh++) {
            float l = lsum[mt][hh];
            l += __shfl_xor_sync(0xffffffffu, l, 1);
            l += __shfl_xor_sync(0xffffffffu, l, 2);
            inv[mt][hh] = 1.f / l;
        }
    __syncthreads();   // done with K/V smem; reuse as half staging [128][80]
#pragma unroll
    for (int mt = 0; mt < 2; mt++) {
        int r0 = rb + mt * 16 + g;
#pragma unroll
        for (int nt = 0; nt < 8; nt++) {
            *(uint32_t*)(smraw + (r0 * 80 + nt * 8 + 2 * tg) * 2) =
                f2h2(co[mt][nt][0] * inv[mt][0], co[mt][nt][1] * inv[mt][0]);
            *(uint32_t*)(smraw + ((r0 + 8) * 80 + nt * 8 + 2 * tg) * 2) =
                f2h2(co[mt][nt][2] * inv[mt][1], co[mt][nt][3] * inv[mt][1]);
        }
    }
    __syncthreads();
    {
        int rg = qt * 128 + t;
        int p  = h * 1024 + (rg >> 2);
        int s  = rg & 3;
        __half* dst = g_o_h + ((size_t)n * HW + p) * C + s * 64;
#pragma unroll
        for (int j = 0; j < 8; j++)
            *(uint4*)&dst[8 * j] = *(uint4*)(smraw + (t * 80 + 8 * j) * 2);
    }
}

// ---------------------------------------------------------------------------
// BatchNorm statistics -> per-channel scale/shift
// ---------------------------------------------------------------------------
__global__ void bn_stats(const float* __restrict__ x,
                         const float* __restrict__ gamma,
                         const float* __restrict__ beta) {
    int c = blockIdx.x;
    int t = threadIdx.x;
    float s = 0.f, s2 = 0.f;
    for (int n = 0; n < N_IMG; n++) {
        const float* p = x + ((size_t)n * C + c) * HW;
        for (int i = t; i < HW; i += 256) {
            float v = p[i];
            s += v;
            s2 += v * v;
        }
    }
    __shared__ float sh0[256], sh1[256];
    sh0[t] = s; sh1[t] = s2;
    __syncthreads();
    for (int o = 128; o > 0; o >>= 1) {
        if (t < o) { sh0[t] += sh0[t + o]; sh1[t] += sh1[t + o]; }
        __syncthreads();
    }
    if (t == 0) {
        const float inv = 1.f / (float)(N_IMG * HW);
        float mean = sh0[0] * inv;
        float var  = sh1[0] * inv - mean * mean;
        float rstd = rsqrtf(var + 1e-5f);
        float sc   = gamma[c] * rstd;
        g_scale[c] = sc;
        g_shift[c] = beta[c] - mean * sc;
    }
}

// ---------------------------------------------------------------------------
// Normalize + transpose (n,c,hw) -> (n,hw,c) as half
// ---------------------------------------------------------------------------
__global__ void norm_transpose(const float* __restrict__ x) {
    __shared__ float tile[32][33];
    int n  = blockIdx.z;
    int c0 = blockIdx.y * 32;
    int p0 = blockIdx.x * 32;
    int tx = threadIdx.x, ty = threadIdx.y;  // 32 x 8
#pragma unroll
    for (int j = 0; j < 4; j++) {
        int c = c0 + ty + j * 8;
        tile[ty + j * 8][tx] =
            x[((size_t)n * C + c) * HW + p0 + tx] * g_scale[c] + g_shift[c];
    }
    __syncthreads();
#pragma unroll
    for (int j = 0; j < 4; j++) {
        int p = p0 + ty + j * 8;
        g_seq_h[((size_t)n * HW + p) * C + c0 + tx] = __float2half_rn(tile[tx][ty + j * 8]);
    }
}

// ---------------------------------------------------------------------------
// Weight pre-conversion (once per launch; deterministic)
// ---------------------------------------------------------------------------
__global__ void convert_w(const float* __restrict__ qkv_w,
                          const float* __restrict__ proj_w) {
    int i = blockIdx.x * 256 + threadIdx.x;
    if (i < C * THREE_C) g_wq_h[i] = __float2half_rn(qkv_w[i]);
    int j = i - C * THREE_C;
    if (j >= 0 && j < C * C) g_wp_h[j] = __float2half_rn(proj_w[j]);
}

// ---------------------------------------------------------------------------
extern "C" void kernel_launch(void* const* d_in, const int* in_sizes, int n_in,
                              void* d_out, int out_size) {
    const float* x      = (const float*)d_in[0];
    const float* gamma  = (const float*)d_in[1];
    const float* beta   = (const float*)d_in[2];
    const float* qkv_w  = (const float*)d_in[3];
    const float* proj_w = (const float*)d_in[4];
    const float* proj_b = (const float*)d_in[5];
    float* out = (float*)d_out;

    cudaFuncSetAttribute(gemm_qkv_h,
                         cudaFuncAttributeMaxDynamicSharedMemorySize, QK_SMEM);
    cudaFuncSetAttribute(gemm_proj_h,
                         cudaFuncAttributeMaxDynamicSharedMemorySize, PJ_SMEM);
    cudaFuncSetAttribute(attn_mma,
                         cudaFuncAttributeMaxDynamicSharedMemorySize, SMEM_ATTN_B);

    bn_stats<<<256, 256>>>(x, gamma, beta);
    norm_transpose<<<dim3(128, 8, 4), dim3(32, 8)>>>(x);
    convert_w<<<(C * THREE_C + C * C) / 256, 256>>>(qkv_w, proj_w);
    gemm_qkv_h<<<dim3(6, 128), 256, QK_SMEM>>>();
    attn_mma<<<dim3(32, 16), 128, SMEM_ATTN_B>>>();
    gemm_proj_h<<<dim3(2, 128), 256, PJ_SMEM>>>(proj_b, out);
}